// round 9
// baseline (speedup 1.0000x reference)
#include <cuda_runtime.h>
#include <cuda_bf16.h>
#include <mma.h>
#include <math.h>
#include <stdint.h>

using namespace nvcuda;

#define HDIM 128
#define MAXN 100000
#define MAXE 1600000
#define POOL_SPLIT 8
#define NUM_GRAPHS 100
#define SCAN_BLK 256
#define MAX_BLKS 512

// smem layout (bytes). ldm = 136 bf16 (272B rows)
#define LDA 136
#define SA_HI 0
#define SA_LO (128 * LDA * 2)
#define SB_HI (2 * 128 * LDA * 2)
#define SB_LO (3 * 128 * LDA * 2)
#define SMEM_MMA (4 * 128 * LDA * 2)   // 139264 bytes

// ---------------- scratch (no allocation allowed) ----------------
__device__ float g_V1[MAXN * HDIM];                // V buffers (ns-scaled GEMM out)
__device__ float g_V2[MAXN * HDIM];
__device__ float g_hA[MAXN * HDIM];                // final h (fp32, for pool)
__device__ __nv_bfloat16 g_Whi[3 * HDIM * HDIM];   // W hi  [k][n]
__device__ __nv_bfloat16 g_Wlo[3 * HDIM * HDIM];   // W lo  [k][n]
__device__ float g_ns[MAXN];
__device__ float g_nd[MAXN];
__device__ int   g_odeg[MAXN];
__device__ int   g_ideg[MAXN];
__device__ int   g_off[MAXN];
__device__ int   g_cursor[MAXN];
__device__ int   g_csr_src[MAXE];
__device__ int   g_bsums[MAX_BLKS];

// ---------------- degree counting ----------------
__global__ void zero_deg_kernel(int* odeg, int* ideg, int N) {
    int i = blockIdx.x * blockDim.x + threadIdx.x;
    if (i < N) { odeg[i] = 0; ideg[i] = 0; }
}

__global__ void count_deg_kernel(const int* __restrict__ src,
                                 const int* __restrict__ dst,
                                 int* odeg, int* ideg, int E) {
    int i = blockIdx.x * blockDim.x + threadIdx.x;
    if (i < E) {
        atomicAdd(&odeg[src[i]], 1);
        atomicAdd(&ideg[dst[i]], 1);
    }
}

__global__ void norms_kernel(const int* __restrict__ odeg,
                             const int* __restrict__ ideg,
                             float* ns, float* nd, int N) {
    int i = blockIdx.x * blockDim.x + threadIdx.x;
    if (i < N) {
        ns[i] = rsqrtf((float)(odeg[i] + 1));
        nd[i] = rsqrtf((float)(ideg[i] + 1));
    }
}

// ---------------- prefix sum ----------------
__global__ void blocksum_kernel(const int* __restrict__ deg, int* bsums, int N) {
    __shared__ int s[SCAN_BLK];
    int i = blockIdx.x * SCAN_BLK + threadIdx.x;
    s[threadIdx.x] = (i < N) ? deg[i] : 0;
    __syncthreads();
    for (int o = SCAN_BLK / 2; o > 0; o >>= 1) {
        if (threadIdx.x < o) s[threadIdx.x] += s[threadIdx.x + o];
        __syncthreads();
    }
    if (threadIdx.x == 0) bsums[blockIdx.x] = s[0];
}

__global__ void scan_bsums_kernel(int* bsums, int nblk) {
    __shared__ int s[MAX_BLKS];
    int t = threadIdx.x;
    int v = (t < nblk) ? bsums[t] : 0;
    s[t] = v;
    __syncthreads();
    for (int o = 1; o < MAX_BLKS; o <<= 1) {
        int add = (t >= o) ? s[t - o] : 0;
        __syncthreads();
        s[t] += add;
        __syncthreads();
    }
    if (t < nblk) bsums[t] = s[t] - v;
}

__global__ void write_offsets_kernel(const int* __restrict__ deg,
                                     const int* __restrict__ bsums,
                                     int* off, int* cursor, int N) {
    __shared__ int s[SCAN_BLK];
    int i = blockIdx.x * SCAN_BLK + threadIdx.x;
    int t = threadIdx.x;
    int v = (i < N) ? deg[i] : 0;
    s[t] = v;
    __syncthreads();
    for (int o = 1; o < SCAN_BLK; o <<= 1) {
        int add = (t >= o) ? s[t - o] : 0;
        __syncthreads();
        s[t] += add;
        __syncthreads();
    }
    if (i < N) {
        int ofs = bsums[blockIdx.x] + s[t] - v;
        off[i] = ofs;
        cursor[i] = ofs;
    }
}

__global__ void fill_csr_kernel(const int* __restrict__ src,
                                const int* __restrict__ dst,
                                int* cursor, int* csr_src, int E) {
    int i = blockIdx.x * blockDim.x + threadIdx.x;
    if (i < E) {
        int slot = atomicAdd(&cursor[dst[i]], 1);
        csr_src[slot] = src[i];
    }
}

// ---------------- convert W: hi/lo split ----------------
__global__ void convertW_kernel(const float* __restrict__ W1,
                                const float* __restrict__ W2,
                                const float* __restrict__ W3,
                                __nv_bfloat16* __restrict__ Whi,
                                __nv_bfloat16* __restrict__ Wlo) {
    int i = blockIdx.x * blockDim.x + threadIdx.x;
    if (i >= 3 * HDIM * HDIM) return;
    int w = i / (HDIM * HDIM);
    int r = i % (HDIM * HDIM);
    const float* W = (w == 0) ? W1 : ((w == 1) ? W2 : W3);
    float v = W[r];
    __nv_bfloat16 hi = __float2bfloat16(v);
    Whi[i] = hi;
    Wlo[i] = __float2bfloat16(v - __bfloat162float(hi));
}

// ================= shared wmma core (device inline) =================
__device__ __forceinline__ void wmma_core_and_scaled_store(
    char* smem, const float* __restrict__ rowscale,
    float* __restrict__ Vout, int base, int N, int tid) {
    __nv_bfloat16* sAhi = (__nv_bfloat16*)(smem + SA_HI);
    __nv_bfloat16* sAlo = (__nv_bfloat16*)(smem + SA_LO);
    __nv_bfloat16* sBhi = (__nv_bfloat16*)(smem + SB_HI);
    __nv_bfloat16* sBlo = (__nv_bfloat16*)(smem + SB_LO);

    const int wid = tid >> 5;
    const int wm = wid & 3;
    const int wn = wid >> 2;

    wmma::fragment<wmma::accumulator, 16, 16, 16, float> acc[2][2];
    #pragma unroll
    for (int i = 0; i < 2; i++)
        #pragma unroll
        for (int j = 0; j < 2; j++)
            wmma::fill_fragment(acc[i][j], 0.0f);

    #pragma unroll
    for (int ks = 0; ks < 8; ks++) {
        wmma::fragment<wmma::matrix_a, 16, 16, 16, __nv_bfloat16, wmma::row_major> ahi[2], alo[2];
        wmma::fragment<wmma::matrix_b, 16, 16, 16, __nv_bfloat16, wmma::row_major> bhi[2], blo[2];
        #pragma unroll
        for (int i = 0; i < 2; i++) {
            wmma::load_matrix_sync(ahi[i], &sAhi[(wm * 32 + i * 16) * LDA + ks * 16], LDA);
            wmma::load_matrix_sync(alo[i], &sAlo[(wm * 32 + i * 16) * LDA + ks * 16], LDA);
        }
        #pragma unroll
        for (int j = 0; j < 2; j++) {
            wmma::load_matrix_sync(bhi[j], &sBhi[(ks * 16) * LDA + wn * 32 + j * 16], LDA);
            wmma::load_matrix_sync(blo[j], &sBlo[(ks * 16) * LDA + wn * 32 + j * 16], LDA);
        }
        #pragma unroll
        for (int i = 0; i < 2; i++)
            #pragma unroll
            for (int j = 0; j < 2; j++) {
                wmma::mma_sync(acc[i][j], ahi[i], bhi[j], acc[i][j]);
                wmma::mma_sync(acc[i][j], ahi[i], blo[j], acc[i][j]);
                wmma::mma_sync(acc[i][j], alo[i], bhi[j], acc[i][j]);
            }
    }

    // stage via smem (aliases sA region; wmma loads are done), apply rowscale
    __syncthreads();
    float* fs = (float*)smem;   // 64 KB
    #pragma unroll
    for (int i = 0; i < 2; i++)
        #pragma unroll
        for (int j = 0; j < 2; j++)
            wmma::store_matrix_sync(
                fs + (wm * 32 + i * 16) * HDIM + wn * 32 + j * 16,
                acc[i][j], HDIM, wmma::mem_row_major);
    __syncthreads();
    float4* V4 = (float4*)Vout;
    const float4* fs4 = (const float4*)fs;
    for (int i = tid; i < 128 * 32; i += 512) {
        int row = i >> 5;
        int gr = base + row;
        if (gr < N) {
            float4 v = fs4[i];
            float s = rowscale[gr];
            v.x *= s; v.y *= s; v.z *= s; v.w *= s;
            V4[(size_t)gr * 32 + (i & 31)] = v;
        }
    }
}

// ---------------- GEMM1: V1 = ns ⊙ (X @ W1), fused fp32->bf16 staging ------
__global__ void __launch_bounds__(512)
gemm1_kernel(const float* __restrict__ Xf32,
             const __nv_bfloat16* __restrict__ Whi,
             const __nv_bfloat16* __restrict__ Wlo,
             const float* __restrict__ ns,
             float* __restrict__ Vout, int N) {
    extern __shared__ char smem[];
    __nv_bfloat16* sAhi = (__nv_bfloat16*)(smem + SA_HI);
    __nv_bfloat16* sAlo = (__nv_bfloat16*)(smem + SA_LO);
    __nv_bfloat16* sBhi = (__nv_bfloat16*)(smem + SB_HI);
    __nv_bfloat16* sBlo = (__nv_bfloat16*)(smem + SB_LO);

    const int tid = threadIdx.x;
    const int base = blockIdx.x * 128;

    const uint4* WH4 = (const uint4*)Whi;
    const uint4* WL4 = (const uint4*)Wlo;
    #pragma unroll
    for (int i = tid; i < 128 * 16; i += 512) {
        int row = i >> 4, c8 = i & 15;
        *(uint4*)&sBhi[row * LDA + c8 * 8] = WH4[i];
        *(uint4*)&sBlo[row * LDA + c8 * 8] = WL4[i];
    }

    const float4* X4 = (const float4*)Xf32;
    #pragma unroll
    for (int i = tid; i < 128 * 32; i += 512) {
        int row = i >> 5, c4 = i & 31;
        int gr = base + row;
        float4 v = make_float4(0.f, 0.f, 0.f, 0.f);
        if (gr < N) v = X4[(size_t)gr * 32 + c4];
        __nv_bfloat16 h0 = __float2bfloat16(v.x);
        __nv_bfloat16 h1 = __float2bfloat16(v.y);
        __nv_bfloat16 h2 = __float2bfloat16(v.z);
        __nv_bfloat16 h3 = __float2bfloat16(v.w);
        __nv_bfloat162* ph = (__nv_bfloat162*)&sAhi[row * LDA + c4 * 4];
        __nv_bfloat162* pl = (__nv_bfloat162*)&sAlo[row * LDA + c4 * 4];
        ph[0] = __halves2bfloat162(h0, h1);
        ph[1] = __halves2bfloat162(h2, h3);
        pl[0] = __halves2bfloat162(
            __float2bfloat16(v.x - __bfloat162float(h0)),
            __float2bfloat16(v.y - __bfloat162float(h1)));
        pl[1] = __halves2bfloat162(
            __float2bfloat16(v.z - __bfloat162float(h2)),
            __float2bfloat16(v.w - __bfloat162float(h3)));
    }
    __syncthreads();
    wmma_core_and_scaled_store(smem, ns, Vout, base, N, tid);
}

// ---------------- fused layer: gather + epilogue + GEMM + ns-scaled out ----
// For rows [base, base+128):
//   h = relu(nd ⊙ (V[self] + sum_{s in in(n)} V[s]) + b)   (V pre-scaled by ns)
//   Vout = ns ⊙ (h @ W)
__global__ void __launch_bounds__(512)
fused_layer_kernel(const float* __restrict__ V,
                   const int* __restrict__ off,
                   const int* __restrict__ ideg,
                   const int* __restrict__ csr_src,
                   const float* __restrict__ ns,
                   const float* __restrict__ nd,
                   const float* __restrict__ b,
                   const __nv_bfloat16* __restrict__ Whi,
                   const __nv_bfloat16* __restrict__ Wlo,
                   float* __restrict__ Vout, int N) {
    extern __shared__ char smem[];
    __nv_bfloat16* sAhi = (__nv_bfloat16*)(smem + SA_HI);
    __nv_bfloat16* sAlo = (__nv_bfloat16*)(smem + SA_LO);
    __nv_bfloat16* sBhi = (__nv_bfloat16*)(smem + SB_HI);
    __nv_bfloat16* sBlo = (__nv_bfloat16*)(smem + SB_LO);

    const int tid = threadIdx.x;
    const int base = blockIdx.x * 128;
    const int wid = tid >> 5;
    const int lane = tid & 31;

    // stage W first (overlaps with gather latency below)
    const uint4* WH4 = (const uint4*)Whi;
    const uint4* WL4 = (const uint4*)Wlo;
    #pragma unroll
    for (int i = tid; i < 128 * 16; i += 512) {
        int row = i >> 4, c8 = i & 15;
        *(uint4*)&sBhi[row * LDA + c8 * 8] = WH4[i];
        *(uint4*)&sBlo[row * LDA + c8 * 8] = WL4[i];
    }

    // gather phase: warp w handles local rows w*8 .. w*8+7
    const float4* V4 = (const float4*)V;
    const float4 bb = ((const float4*)b)[lane];
    #pragma unroll
    for (int r = 0; r < 8; r++) {
        int row = wid * 8 + r;
        int n = base + row;
        float hx = 0.f, hy = 0.f, hz = 0.f, hw = 0.f;
        if (n < N) {
            float4 acc = V4[(size_t)n * 32 + lane];   // self (pre-scaled)
            int o = off[n];
            int d = ideg[n];
            int e = 0;
            for (; e + 4 <= d; e += 4) {
                int s0 = csr_src[o + e + 0];
                int s1 = csr_src[o + e + 1];
                int s2 = csr_src[o + e + 2];
                int s3 = csr_src[o + e + 3];
                float4 v0 = __ldg(&V4[(size_t)s0 * 32 + lane]);
                float4 v1 = __ldg(&V4[(size_t)s1 * 32 + lane]);
                float4 v2 = __ldg(&V4[(size_t)s2 * 32 + lane]);
                float4 v3 = __ldg(&V4[(size_t)s3 * 32 + lane]);
                acc.x += v0.x + v1.x + v2.x + v3.x;
                acc.y += v0.y + v1.y + v2.y + v3.y;
                acc.z += v0.z + v1.z + v2.z + v3.z;
                acc.w += v0.w + v1.w + v2.w + v3.w;
            }
            for (; e < d; e++) {
                int s = csr_src[o + e];
                float4 v = __ldg(&V4[(size_t)s * 32 + lane]);
                acc.x += v.x; acc.y += v.y; acc.z += v.z; acc.w += v.w;
            }
            float sc = nd[n];
            hx = fmaxf(acc.x * sc + bb.x, 0.f);
            hy = fmaxf(acc.y * sc + bb.y, 0.f);
            hz = fmaxf(acc.z * sc + bb.z, 0.f);
            hw = fmaxf(acc.w * sc + bb.w, 0.f);
        }
        // split h into bf16 hi/lo directly in wmma staging smem
        __nv_bfloat16 h0 = __float2bfloat16(hx);
        __nv_bfloat16 h1 = __float2bfloat16(hy);
        __nv_bfloat16 h2 = __float2bfloat16(hz);
        __nv_bfloat16 h3 = __float2bfloat16(hw);
        __nv_bfloat162* ph = (__nv_bfloat162*)&sAhi[row * LDA + lane * 4];
        __nv_bfloat162* pl = (__nv_bfloat162*)&sAlo[row * LDA + lane * 4];
        ph[0] = __halves2bfloat162(h0, h1);
        ph[1] = __halves2bfloat162(h2, h3);
        pl[0] = __halves2bfloat162(
            __float2bfloat16(hx - __bfloat162float(h0)),
            __float2bfloat16(hy - __bfloat162float(h1)));
        pl[1] = __halves2bfloat162(
            __float2bfloat16(hz - __bfloat162float(h2)),
            __float2bfloat16(hw - __bfloat162float(h3)));
    }
    __syncthreads();
    wmma_core_and_scaled_store(smem, ns, Vout, base, N, tid);
}

// ---------------- final gather: h = relu(nd⊙(sum V)+b), fp32 out ----------
__global__ void gather_final_kernel(const float* __restrict__ V,
                                    const int* __restrict__ off,
                                    const int* __restrict__ ideg,
                                    const int* __restrict__ csr_src,
                                    const float* __restrict__ nd,
                                    const float* __restrict__ b,
                                    float* __restrict__ hout, int N) {
    int gt = blockIdx.x * blockDim.x + threadIdx.x;
    int n = gt >> 5;
    int lane = threadIdx.x & 31;
    if (n >= N) return;

    const float4* V4 = (const float4*)V;
    float4 acc = V4[(size_t)n * 32 + lane];
    int o = off[n];
    int d = ideg[n];
    int e = 0;
    for (; e + 4 <= d; e += 4) {
        int s0 = csr_src[o + e + 0];
        int s1 = csr_src[o + e + 1];
        int s2 = csr_src[o + e + 2];
        int s3 = csr_src[o + e + 3];
        float4 v0 = __ldg(&V4[(size_t)s0 * 32 + lane]);
        float4 v1 = __ldg(&V4[(size_t)s1 * 32 + lane]);
        float4 v2 = __ldg(&V4[(size_t)s2 * 32 + lane]);
        float4 v3 = __ldg(&V4[(size_t)s3 * 32 + lane]);
        acc.x += v0.x + v1.x + v2.x + v3.x;
        acc.y += v0.y + v1.y + v2.y + v3.y;
        acc.z += v0.z + v1.z + v2.z + v3.z;
        acc.w += v0.w + v1.w + v2.w + v3.w;
    }
    for (; e < d; e++) {
        int s = csr_src[o + e];
        float4 v = __ldg(&V4[(size_t)s * 32 + lane]);
        acc.x += v.x; acc.y += v.y; acc.z += v.z; acc.w += v.w;
    }

    float sc = nd[n];
    float4 bb = ((const float4*)b)[lane];
    acc.x = fmaxf(acc.x * sc + bb.x, 0.f);
    acc.y = fmaxf(acc.y * sc + bb.y, 0.f);
    acc.z = fmaxf(acc.z * sc + bb.z, 0.f);
    acc.w = fmaxf(acc.w * sc + bb.w, 0.f);
    ((float4*)hout)[(size_t)n * 32 + lane] = acc;
}

// ---------------- output zero init ----------------
__global__ void zero_out_kernel(float* out, int n) {
    int i = blockIdx.x * blockDim.x + threadIdx.x;
    if (i < n) out[i] = 0.f;
}

// ---------------- pooling ----------------
__global__ void pool_kernel(const float* __restrict__ h,
                            const int* __restrict__ gid,
                            const float* __restrict__ Wp,
                            const float* __restrict__ bp,
                            float* __restrict__ out, int N) {
    const int g    = blockIdx.x / POOL_SPLIT;
    const int part = blockIdx.x % POOL_SPLIT;
    const int tid  = threadIdx.x;

    int lo = 0, hi = N;
    while (lo < hi) { int m = (lo + hi) >> 1; if (gid[m] < g) lo = m + 1; else hi = m; }
    int start = lo;
    lo = start; hi = N;
    while (lo < hi) { int m = (lo + hi) >> 1; if (gid[m] < g + 1) lo = m + 1; else hi = m; }
    int end = lo;

    __shared__ float sWp[HDIM];
    __shared__ float red[4];
    __shared__ float sdot;
    sWp[tid] = Wp[tid];
    float bpv = bp[0];
    __syncthreads();

    float lsum = 0.f;
    float lmax = 0.f;
    const int lane = tid & 31;
    const int warp = tid >> 5;

    for (int n = start + part; n < end; n += POOL_SPLIT) {
        float val = h[n * HDIM + tid];
        float p = val * sWp[tid];
        #pragma unroll
        for (int o = 16; o > 0; o >>= 1)
            p += __shfl_down_sync(0xFFFFFFFFu, p, o);
        if (lane == 0) red[warp] = p;
        __syncthreads();
        if (tid == 0) sdot = red[0] + red[1] + red[2] + red[3] + bpv;
        __syncthreads();
        float w = 1.0f / (1.0f + expf(-sdot));
        lsum += val * w;
        lmax = fmaxf(lmax, val);
        __syncthreads();
    }

    if (end > start) {
        atomicAdd(&out[g * 2 * HDIM + tid], lsum);
        atomicMax((int*)&out[g * 2 * HDIM + HDIM + tid], __float_as_int(lmax));
    }
}

// ---------------- launch ----------------
extern "C" void kernel_launch(void* const* d_in, const int* in_sizes, int n_in,
                              void* d_out, int out_size) {
    const float* node_feats = (const float*)d_in[0];
    const int*   src        = (const int*)d_in[1];
    const int*   dst        = (const int*)d_in[2];
    const int*   gid        = (const int*)d_in[3];
    const float* W1 = (const float*)d_in[4];  const float* b1 = (const float*)d_in[5];
    const float* W2 = (const float*)d_in[6];  const float* b2 = (const float*)d_in[7];
    const float* W3 = (const float*)d_in[8];  const float* b3 = (const float*)d_in[9];
    const float* Wp = (const float*)d_in[10]; const float* bp = (const float*)d_in[11];
    float* out = (float*)d_out;

    const int N = in_sizes[0] / HDIM;
    const int E = in_sizes[1];

    float *pV1, *pV2, *phA, *pns, *pnd;
    __nv_bfloat16 *pWhi, *pWlo;
    int *pod, *pid_, *poff, *pcur, *pcsr, *pbs;
    cudaGetSymbolAddress((void**)&pV1,  g_V1);
    cudaGetSymbolAddress((void**)&pV2,  g_V2);
    cudaGetSymbolAddress((void**)&phA,  g_hA);
    cudaGetSymbolAddress((void**)&pWhi, g_Whi);
    cudaGetSymbolAddress((void**)&pWlo, g_Wlo);
    cudaGetSymbolAddress((void**)&pns, g_ns);
    cudaGetSymbolAddress((void**)&pnd, g_nd);
    cudaGetSymbolAddress((void**)&pod, g_odeg);
    cudaGetSymbolAddress((void**)&pid_, g_ideg);
    cudaGetSymbolAddress((void**)&poff, g_off);
    cudaGetSymbolAddress((void**)&pcur, g_cursor);
    cudaGetSymbolAddress((void**)&pcsr, g_csr_src);
    cudaGetSymbolAddress((void**)&pbs, g_bsums);

    cudaFuncSetAttribute(gemm1_kernel,
                         cudaFuncAttributeMaxDynamicSharedMemorySize, SMEM_MMA);
    cudaFuncSetAttribute(fused_layer_kernel,
                         cudaFuncAttributeMaxDynamicSharedMemorySize, SMEM_MMA);

    const int nblk_scan = (N + SCAN_BLK - 1) / SCAN_BLK;
    const int gemm_grid = (N + 127) / 128;
    const int gather_blocks = (int)(((long long)N * 32 + 255) / 256);

    // --- fork: norm+CSR build on side stream; convertW + GEMM1 on main ---
    cudaStream_t sB;
    cudaStreamCreateWithFlags(&sB, cudaStreamNonBlocking);
    cudaEvent_t evFork, evNorms, evJoin;
    cudaEventCreateWithFlags(&evFork,  cudaEventDisableTiming);
    cudaEventCreateWithFlags(&evNorms, cudaEventDisableTiming);
    cudaEventCreateWithFlags(&evJoin,  cudaEventDisableTiming);

    cudaEventRecord(evFork, 0);
    cudaStreamWaitEvent(sB, evFork, 0);

    zero_deg_kernel<<<(N + 255) / 256, 256, 0, sB>>>(pod, pid_, N);
    count_deg_kernel<<<(E + 255) / 256, 256, 0, sB>>>(src, dst, pod, pid_, E);
    norms_kernel<<<(N + 255) / 256, 256, 0, sB>>>(pod, pid_, pns, pnd, N);
    cudaEventRecord(evNorms, sB);
    blocksum_kernel<<<nblk_scan, SCAN_BLK, 0, sB>>>(pid_, pbs, N);
    scan_bsums_kernel<<<1, MAX_BLKS, 0, sB>>>(pbs, nblk_scan);
    write_offsets_kernel<<<nblk_scan, SCAN_BLK, 0, sB>>>(pid_, pbs, poff, pcur, N);
    fill_csr_kernel<<<(E + 255) / 256, 256, 0, sB>>>(src, dst, pcur, pcsr, E);
    zero_out_kernel<<<(out_size + 255) / 256, 256, 0, sB>>>(out, out_size);
    cudaEventRecord(evJoin, sB);

    // main: convertW, then GEMM1 (needs ns for row-scale epilogue only)
    convertW_kernel<<<(3 * HDIM * HDIM + 255) / 256, 256>>>(W1, W2, W3, pWhi, pWlo);
    cudaStreamWaitEvent(0, evNorms, 0);
    gemm1_kernel<<<gemm_grid, 512, SMEM_MMA>>>(node_feats, pWhi, pWlo, pns, pV1, N);

    cudaStreamWaitEvent(0, evJoin, 0);   // fused layers need CSR

    // --- fused layers 2, 3 (gather + epilogue + GEMM + ns-scaled out) ---
    fused_layer_kernel<<<gemm_grid, 512, SMEM_MMA>>>(
        pV1, poff, pid_, pcsr, pns, pnd, b1,
        pWhi + HDIM * HDIM, pWlo + HDIM * HDIM, pV2, N);
    fused_layer_kernel<<<gemm_grid, 512, SMEM_MMA>>>(
        pV2, poff, pid_, pcsr, pns, pnd, b2,
        pWhi + 2 * HDIM * HDIM, pWlo + 2 * HDIM * HDIM, pV1, N);

    // --- final gather (fp32 h) + pool ---
    gather_final_kernel<<<gather_blocks, 256>>>(pV1, poff, pid_, pcsr,
                                                pnd, b3, phA, N);
    pool_kernel<<<NUM_GRAPHS * POOL_SPLIT, HDIM>>>(phA, gid, Wp, bp, out, N);
    // single side stream + 3 events, not destroyed (capture safety)
}

// round 10
// speedup vs baseline: 1.1293x; 1.1293x over previous
#include <cuda_runtime.h>
#include <cuda_bf16.h>
#include <mma.h>
#include <math.h>
#include <stdint.h>

using namespace nvcuda;

#define HDIM 128
#define MAXN 100000
#define MAXE 1600000
#define POOL_SPLIT 8
#define NUM_GRAPHS 100
#define SCAN_BLK 256
#define MAX_BLKS 512

// smem layout (bytes). ldm = 136 bf16 (272B rows)
#define LDA 136
#define SA_HI 0
#define SA_LO (128 * LDA * 2)
#define SB_HI (2 * 128 * LDA * 2)
#define SB_LO (3 * 128 * LDA * 2)
#define SMEM_MMA (4 * 128 * LDA * 2)   // 139264 bytes

// ---------------- scratch (no allocation allowed) ----------------
__device__ float g_V[MAXN * HDIM];                 // V = ns ⊙ (GEMM out), fp32
__device__ float g_hA[MAXN * HDIM];                // final h (fp32, for pool)
__device__ __nv_bfloat16 g_uhi[MAXN * HDIM];       // h hi (GEMM input)
__device__ __nv_bfloat16 g_ulo[MAXN * HDIM];       // h lo
__device__ __nv_bfloat16 g_Whi[3 * HDIM * HDIM];   // W hi  [k][n]
__device__ __nv_bfloat16 g_Wlo[3 * HDIM * HDIM];   // W lo  [k][n]
__device__ float g_ns[MAXN];
__device__ float g_nd[MAXN];
__device__ int   g_odeg[MAXN];
__device__ int   g_ideg[MAXN];
__device__ int   g_off[MAXN];
__device__ int   g_cursor[MAXN];
__device__ int   g_csr_src[MAXE];
__device__ int   g_bsums[MAX_BLKS];

// ---------------- degree counting ----------------
__global__ void zero_deg_kernel(int* odeg, int* ideg, int N) {
    int i = blockIdx.x * blockDim.x + threadIdx.x;
    if (i < N) { odeg[i] = 0; ideg[i] = 0; }
}

__global__ void count_deg_kernel(const int* __restrict__ src,
                                 const int* __restrict__ dst,
                                 int* odeg, int* ideg, int E) {
    int i = blockIdx.x * blockDim.x + threadIdx.x;
    if (i < E) {
        atomicAdd(&odeg[src[i]], 1);
        atomicAdd(&ideg[dst[i]], 1);
    }
}

__global__ void norms_kernel(const int* __restrict__ odeg,
                             const int* __restrict__ ideg,
                             float* ns, float* nd, int N) {
    int i = blockIdx.x * blockDim.x + threadIdx.x;
    if (i < N) {
        ns[i] = rsqrtf((float)(odeg[i] + 1));
        nd[i] = rsqrtf((float)(ideg[i] + 1));
    }
}

// ---------------- prefix sum ----------------
__global__ void blocksum_kernel(const int* __restrict__ deg, int* bsums, int N) {
    __shared__ int s[SCAN_BLK];
    int i = blockIdx.x * SCAN_BLK + threadIdx.x;
    s[threadIdx.x] = (i < N) ? deg[i] : 0;
    __syncthreads();
    for (int o = SCAN_BLK / 2; o > 0; o >>= 1) {
        if (threadIdx.x < o) s[threadIdx.x] += s[threadIdx.x + o];
        __syncthreads();
    }
    if (threadIdx.x == 0) bsums[blockIdx.x] = s[0];
}

__global__ void scan_bsums_kernel(int* bsums, int nblk) {
    __shared__ int s[MAX_BLKS];
    int t = threadIdx.x;
    int v = (t < nblk) ? bsums[t] : 0;
    s[t] = v;
    __syncthreads();
    for (int o = 1; o < MAX_BLKS; o <<= 1) {
        int add = (t >= o) ? s[t - o] : 0;
        __syncthreads();
        s[t] += add;
        __syncthreads();
    }
    if (t < nblk) bsums[t] = s[t] - v;
}

__global__ void write_offsets_kernel(const int* __restrict__ deg,
                                     const int* __restrict__ bsums,
                                     int* off, int* cursor, int N) {
    __shared__ int s[SCAN_BLK];
    int i = blockIdx.x * SCAN_BLK + threadIdx.x;
    int t = threadIdx.x;
    int v = (i < N) ? deg[i] : 0;
    s[t] = v;
    __syncthreads();
    for (int o = 1; o < SCAN_BLK; o <<= 1) {
        int add = (t >= o) ? s[t - o] : 0;
        __syncthreads();
        s[t] += add;
        __syncthreads();
    }
    if (i < N) {
        int ofs = bsums[blockIdx.x] + s[t] - v;
        off[i] = ofs;
        cursor[i] = ofs;
    }
}

__global__ void fill_csr_kernel(const int* __restrict__ src,
                                const int* __restrict__ dst,
                                int* cursor, int* csr_src, int E) {
    int i = blockIdx.x * blockDim.x + threadIdx.x;
    if (i < E) {
        int slot = atomicAdd(&cursor[dst[i]], 1);
        csr_src[slot] = src[i];
    }
}

// ---------------- convert W: hi/lo split ----------------
__global__ void convertW_kernel(const float* __restrict__ W1,
                                const float* __restrict__ W2,
                                const float* __restrict__ W3,
                                __nv_bfloat16* __restrict__ Whi,
                                __nv_bfloat16* __restrict__ Wlo) {
    int i = blockIdx.x * blockDim.x + threadIdx.x;
    if (i >= 3 * HDIM * HDIM) return;
    int w = i / (HDIM * HDIM);
    int r = i % (HDIM * HDIM);
    const float* W = (w == 0) ? W1 : ((w == 1) ? W2 : W3);
    float v = W[r];
    __nv_bfloat16 hi = __float2bfloat16(v);
    Whi[i] = hi;
    Wlo[i] = __float2bfloat16(v - __bfloat162float(hi));
}

// ================= shared wmma core + ns-scaled store =================
__device__ __forceinline__ void wmma_core_and_scaled_store(
    char* smem, const float* __restrict__ rowscale,
    float* __restrict__ Vout, int base, int N, int tid) {
    __nv_bfloat16* sAhi = (__nv_bfloat16*)(smem + SA_HI);
    __nv_bfloat16* sAlo = (__nv_bfloat16*)(smem + SA_LO);
    __nv_bfloat16* sBhi = (__nv_bfloat16*)(smem + SB_HI);
    __nv_bfloat16* sBlo = (__nv_bfloat16*)(smem + SB_LO);

    const int wid = tid >> 5;
    const int wm = wid & 3;
    const int wn = wid >> 2;

    wmma::fragment<wmma::accumulator, 16, 16, 16, float> acc[2][2];
    #pragma unroll
    for (int i = 0; i < 2; i++)
        #pragma unroll
        for (int j = 0; j < 2; j++)
            wmma::fill_fragment(acc[i][j], 0.0f);

    #pragma unroll
    for (int ks = 0; ks < 8; ks++) {
        wmma::fragment<wmma::matrix_a, 16, 16, 16, __nv_bfloat16, wmma::row_major> ahi[2], alo[2];
        wmma::fragment<wmma::matrix_b, 16, 16, 16, __nv_bfloat16, wmma::row_major> bhi[2], blo[2];
        #pragma unroll
        for (int i = 0; i < 2; i++) {
            wmma::load_matrix_sync(ahi[i], &sAhi[(wm * 32 + i * 16) * LDA + ks * 16], LDA);
            wmma::load_matrix_sync(alo[i], &sAlo[(wm * 32 + i * 16) * LDA + ks * 16], LDA);
        }
        #pragma unroll
        for (int j = 0; j < 2; j++) {
            wmma::load_matrix_sync(bhi[j], &sBhi[(ks * 16) * LDA + wn * 32 + j * 16], LDA);
            wmma::load_matrix_sync(blo[j], &sBlo[(ks * 16) * LDA + wn * 32 + j * 16], LDA);
        }
        #pragma unroll
        for (int i = 0; i < 2; i++)
            #pragma unroll
            for (int j = 0; j < 2; j++) {
                wmma::mma_sync(acc[i][j], ahi[i], bhi[j], acc[i][j]);
                wmma::mma_sync(acc[i][j], ahi[i], blo[j], acc[i][j]);
                wmma::mma_sync(acc[i][j], alo[i], bhi[j], acc[i][j]);
            }
    }

    // stage via smem (aliases sA region; wmma loads done), apply rowscale
    __syncthreads();
    float* fs = (float*)smem;   // 64 KB
    #pragma unroll
    for (int i = 0; i < 2; i++)
        #pragma unroll
        for (int j = 0; j < 2; j++)
            wmma::store_matrix_sync(
                fs + (wm * 32 + i * 16) * HDIM + wn * 32 + j * 16,
                acc[i][j], HDIM, wmma::mem_row_major);
    __syncthreads();
    float4* V4 = (float4*)Vout;
    const float4* fs4 = (const float4*)fs;
    for (int i = tid; i < 128 * 32; i += 512) {
        int row = i >> 5;
        int gr = base + row;
        if (gr < N) {
            float4 v = fs4[i];
            float s = rowscale[gr];
            v.x *= s; v.y *= s; v.z *= s; v.w *= s;
            V4[(size_t)gr * 32 + (i & 31)] = v;
        }
    }
}

// ---------------- GEMM1: V = ns ⊙ (X @ W1), fused fp32->bf16 staging ------
__global__ void __launch_bounds__(512)
gemm1_kernel(const float* __restrict__ Xf32,
             const __nv_bfloat16* __restrict__ Whi,
             const __nv_bfloat16* __restrict__ Wlo,
             const float* __restrict__ ns,
             float* __restrict__ Vout, int N) {
    extern __shared__ char smem[];
    __nv_bfloat16* sAhi = (__nv_bfloat16*)(smem + SA_HI);
    __nv_bfloat16* sAlo = (__nv_bfloat16*)(smem + SA_LO);
    __nv_bfloat16* sBhi = (__nv_bfloat16*)(smem + SB_HI);
    __nv_bfloat16* sBlo = (__nv_bfloat16*)(smem + SB_LO);

    const int tid = threadIdx.x;
    const int base = blockIdx.x * 128;

    const uint4* WH4 = (const uint4*)Whi;
    const uint4* WL4 = (const uint4*)Wlo;
    #pragma unroll
    for (int i = tid; i < 128 * 16; i += 512) {
        int row = i >> 4, c8 = i & 15;
        *(uint4*)&sBhi[row * LDA + c8 * 8] = WH4[i];
        *(uint4*)&sBlo[row * LDA + c8 * 8] = WL4[i];
    }

    const float4* X4 = (const float4*)Xf32;
    #pragma unroll
    for (int i = tid; i < 128 * 32; i += 512) {
        int row = i >> 5, c4 = i & 31;
        int gr = base + row;
        float4 v = make_float4(0.f, 0.f, 0.f, 0.f);
        if (gr < N) v = X4[(size_t)gr * 32 + c4];
        __nv_bfloat16 h0 = __float2bfloat16(v.x);
        __nv_bfloat16 h1 = __float2bfloat16(v.y);
        __nv_bfloat16 h2 = __float2bfloat16(v.z);
        __nv_bfloat16 h3 = __float2bfloat16(v.w);
        __nv_bfloat162* ph = (__nv_bfloat162*)&sAhi[row * LDA + c4 * 4];
        __nv_bfloat162* pl = (__nv_bfloat162*)&sAlo[row * LDA + c4 * 4];
        ph[0] = __halves2bfloat162(h0, h1);
        ph[1] = __halves2bfloat162(h2, h3);
        pl[0] = __halves2bfloat162(
            __float2bfloat16(v.x - __bfloat162float(h0)),
            __float2bfloat16(v.y - __bfloat162float(h1)));
        pl[1] = __halves2bfloat162(
            __float2bfloat16(v.z - __bfloat162float(h2)),
            __float2bfloat16(v.w - __bfloat162float(h3)));
    }
    __syncthreads();
    wmma_core_and_scaled_store(smem, ns, Vout, base, N, tid);
}

// ---------------- GEMM mid: V = ns ⊙ (u @ W), u in bf16 hi/lo ----------
__global__ void __launch_bounds__(512)
gemm_mid_kernel(const __nv_bfloat16* __restrict__ Ahi,
                const __nv_bfloat16* __restrict__ Alo,
                const __nv_bfloat16* __restrict__ Whi,
                const __nv_bfloat16* __restrict__ Wlo,
                const float* __restrict__ ns,
                float* __restrict__ Vout, int N) {
    extern __shared__ char smem[];
    __nv_bfloat16* sAhi = (__nv_bfloat16*)(smem + SA_HI);
    __nv_bfloat16* sAlo = (__nv_bfloat16*)(smem + SA_LO);
    __nv_bfloat16* sBhi = (__nv_bfloat16*)(smem + SB_HI);
    __nv_bfloat16* sBlo = (__nv_bfloat16*)(smem + SB_LO);

    const int tid = threadIdx.x;
    const int base = blockIdx.x * 128;

    const uint4* WH4 = (const uint4*)Whi;
    const uint4* WL4 = (const uint4*)Wlo;
    const uint4* AH4 = (const uint4*)Ahi;
    const uint4* AL4 = (const uint4*)Alo;
    const uint4 z4 = make_uint4(0, 0, 0, 0);
    #pragma unroll
    for (int i = tid; i < 128 * 16; i += 512) {
        int row = i >> 4, c8 = i & 15;
        int gr = base + row;
        bool ok = gr < N;
        *(uint4*)&sAhi[row * LDA + c8 * 8] = ok ? AH4[(size_t)gr * 16 + c8] : z4;
        *(uint4*)&sAlo[row * LDA + c8 * 8] = ok ? AL4[(size_t)gr * 16 + c8] : z4;
        *(uint4*)&sBhi[row * LDA + c8 * 8] = WH4[i];
        *(uint4*)&sBlo[row * LDA + c8 * 8] = WL4[i];
    }
    __syncthreads();
    wmma_core_and_scaled_store(smem, ns, Vout, base, N, tid);
}

// ---------------- gather: h = relu(nd⊙(V[n]+sum V[s])+b) -> bf16 hi/lo ----
__global__ void gather_u_kernel(const float* __restrict__ V,
                                const int* __restrict__ off,
                                const int* __restrict__ ideg,
                                const int* __restrict__ csr_src,
                                const float* __restrict__ nd,
                                const float* __restrict__ b,
                                __nv_bfloat16* __restrict__ uhi,
                                __nv_bfloat16* __restrict__ ulo, int N) {
    int gt = blockIdx.x * blockDim.x + threadIdx.x;
    int n = gt >> 5;
    int lane = threadIdx.x & 31;
    if (n >= N) return;

    const float4* V4 = (const float4*)V;
    float4 acc = V4[(size_t)n * 32 + lane];
    int o = off[n];
    int d = ideg[n];
    int e = 0;
    for (; e + 4 <= d; e += 4) {
        int s0 = csr_src[o + e + 0];
        int s1 = csr_src[o + e + 1];
        int s2 = csr_src[o + e + 2];
        int s3 = csr_src[o + e + 3];
        float4 v0 = __ldg(&V4[(size_t)s0 * 32 + lane]);
        float4 v1 = __ldg(&V4[(size_t)s1 * 32 + lane]);
        float4 v2 = __ldg(&V4[(size_t)s2 * 32 + lane]);
        float4 v3 = __ldg(&V4[(size_t)s3 * 32 + lane]);
        acc.x += v0.x + v1.x + v2.x + v3.x;
        acc.y += v0.y + v1.y + v2.y + v3.y;
        acc.z += v0.z + v1.z + v2.z + v3.z;
        acc.w += v0.w + v1.w + v2.w + v3.w;
    }
    for (; e < d; e++) {
        int s = csr_src[o + e];
        float4 v = __ldg(&V4[(size_t)s * 32 + lane]);
        acc.x += v.x; acc.y += v.y; acc.z += v.z; acc.w += v.w;
    }

    float sc = nd[n];
    float4 bb = ((const float4*)b)[lane];
    float hx = fmaxf(acc.x * sc + bb.x, 0.f);
    float hy = fmaxf(acc.y * sc + bb.y, 0.f);
    float hz = fmaxf(acc.z * sc + bb.z, 0.f);
    float hw = fmaxf(acc.w * sc + bb.w, 0.f);

    __nv_bfloat16 h0 = __float2bfloat16(hx);
    __nv_bfloat16 h1 = __float2bfloat16(hy);
    __nv_bfloat16 h2 = __float2bfloat16(hz);
    __nv_bfloat16 h3 = __float2bfloat16(hw);
    __nv_bfloat162* UH = (__nv_bfloat162*)uhi;
    __nv_bfloat162* UL = (__nv_bfloat162*)ulo;
    size_t i2 = (size_t)n * 64 + lane * 2;
    UH[i2 + 0] = __halves2bfloat162(h0, h1);
    UH[i2 + 1] = __halves2bfloat162(h2, h3);
    UL[i2 + 0] = __halves2bfloat162(
        __float2bfloat16(hx - __bfloat162float(h0)),
        __float2bfloat16(hy - __bfloat162float(h1)));
    UL[i2 + 1] = __halves2bfloat162(
        __float2bfloat16(hz - __bfloat162float(h2)),
        __float2bfloat16(hw - __bfloat162float(h3)));
}

// ---------------- final gather: h fp32 for pooling ----------------
__global__ void gather_final_kernel(const float* __restrict__ V,
                                    const int* __restrict__ off,
                                    const int* __restrict__ ideg,
                                    const int* __restrict__ csr_src,
                                    const float* __restrict__ nd,
                                    const float* __restrict__ b,
                                    float* __restrict__ hout, int N) {
    int gt = blockIdx.x * blockDim.x + threadIdx.x;
    int n = gt >> 5;
    int lane = threadIdx.x & 31;
    if (n >= N) return;

    const float4* V4 = (const float4*)V;
    float4 acc = V4[(size_t)n * 32 + lane];
    int o = off[n];
    int d = ideg[n];
    int e = 0;
    for (; e + 4 <= d; e += 4) {
        int s0 = csr_src[o + e + 0];
        int s1 = csr_src[o + e + 1];
        int s2 = csr_src[o + e + 2];
        int s3 = csr_src[o + e + 3];
        float4 v0 = __ldg(&V4[(size_t)s0 * 32 + lane]);
        float4 v1 = __ldg(&V4[(size_t)s1 * 32 + lane]);
        float4 v2 = __ldg(&V4[(size_t)s2 * 32 + lane]);
        float4 v3 = __ldg(&V4[(size_t)s3 * 32 + lane]);
        acc.x += v0.x + v1.x + v2.x + v3.x;
        acc.y += v0.y + v1.y + v2.y + v3.y;
        acc.z += v0.z + v1.z + v2.z + v3.z;
        acc.w += v0.w + v1.w + v2.w + v3.w;
    }
    for (; e < d; e++) {
        int s = csr_src[o + e];
        float4 v = __ldg(&V4[(size_t)s * 32 + lane]);
        acc.x += v.x; acc.y += v.y; acc.z += v.z; acc.w += v.w;
    }

    float sc = nd[n];
    float4 bb = ((const float4*)b)[lane];
    acc.x = fmaxf(acc.x * sc + bb.x, 0.f);
    acc.y = fmaxf(acc.y * sc + bb.y, 0.f);
    acc.z = fmaxf(acc.z * sc + bb.z, 0.f);
    acc.w = fmaxf(acc.w * sc + bb.w, 0.f);
    ((float4*)hout)[(size_t)n * 32 + lane] = acc;
}

// ---------------- output zero init ----------------
__global__ void zero_out_kernel(float* out, int n) {
    int i = blockIdx.x * blockDim.x + threadIdx.x;
    if (i < n) out[i] = 0.f;
}

// ---------------- pooling ----------------
__global__ void pool_kernel(const float* __restrict__ h,
                            const int* __restrict__ gid,
                            const float* __restrict__ Wp,
                            const float* __restrict__ bp,
                            float* __restrict__ out, int N) {
    const int g    = blockIdx.x / POOL_SPLIT;
    const int part = blockIdx.x % POOL_SPLIT;
    const int tid  = threadIdx.x;

    int lo = 0, hi = N;
    while (lo < hi) { int m = (lo + hi) >> 1; if (gid[m] < g) lo = m + 1; else hi = m; }
    int start = lo;
    lo = start; hi = N;
    while (lo < hi) { int m = (lo + hi) >> 1; if (gid[m] < g + 1) lo = m + 1; else hi = m; }
    int end = lo;

    __shared__ float sWp[HDIM];
    __shared__ float red[4];
    __shared__ float sdot;
    sWp[tid] = Wp[tid];
    float bpv = bp[0];
    __syncthreads();

    float lsum = 0.f;
    float lmax = 0.f;
    const int lane = tid & 31;
    const int warp = tid >> 5;

    for (int n = start + part; n < end; n += POOL_SPLIT) {
        float val = h[n * HDIM + tid];
        float p = val * sWp[tid];
        #pragma unroll
        for (int o = 16; o > 0; o >>= 1)
            p += __shfl_down_sync(0xFFFFFFFFu, p, o);
        if (lane == 0) red[warp] = p;
        __syncthreads();
        if (tid == 0) sdot = red[0] + red[1] + red[2] + red[3] + bpv;
        __syncthreads();
        float w = 1.0f / (1.0f + expf(-sdot));
        lsum += val * w;
        lmax = fmaxf(lmax, val);
        __syncthreads();
    }

    if (end > start) {
        atomicAdd(&out[g * 2 * HDIM + tid], lsum);
        atomicMax((int*)&out[g * 2 * HDIM + HDIM + tid], __float_as_int(lmax));
    }
}

// ---------------- launch ----------------
extern "C" void kernel_launch(void* const* d_in, const int* in_sizes, int n_in,
                              void* d_out, int out_size) {
    const float* node_feats = (const float*)d_in[0];
    const int*   src        = (const int*)d_in[1];
    const int*   dst        = (const int*)d_in[2];
    const int*   gid        = (const int*)d_in[3];
    const float* W1 = (const float*)d_in[4];  const float* b1 = (const float*)d_in[5];
    const float* W2 = (const float*)d_in[6];  const float* b2 = (const float*)d_in[7];
    const float* W3 = (const float*)d_in[8];  const float* b3 = (const float*)d_in[9];
    const float* Wp = (const float*)d_in[10]; const float* bp = (const float*)d_in[11];
    float* out = (float*)d_out;

    const int N = in_sizes[0] / HDIM;
    const int E = in_sizes[1];

    float *pV, *phA, *pns, *pnd;
    __nv_bfloat16 *puhi, *pulo, *pWhi, *pWlo;
    int *pod, *pid_, *poff, *pcur, *pcsr, *pbs;
    cudaGetSymbolAddress((void**)&pV,   g_V);
    cudaGetSymbolAddress((void**)&phA,  g_hA);
    cudaGetSymbolAddress((void**)&puhi, g_uhi);
    cudaGetSymbolAddress((void**)&pulo, g_ulo);
    cudaGetSymbolAddress((void**)&pWhi, g_Whi);
    cudaGetSymbolAddress((void**)&pWlo, g_Wlo);
    cudaGetSymbolAddress((void**)&pns, g_ns);
    cudaGetSymbolAddress((void**)&pnd, g_nd);
    cudaGetSymbolAddress((void**)&pod, g_odeg);
    cudaGetSymbolAddress((void**)&pid_, g_ideg);
    cudaGetSymbolAddress((void**)&poff, g_off);
    cudaGetSymbolAddress((void**)&pcur, g_cursor);
    cudaGetSymbolAddress((void**)&pcsr, g_csr_src);
    cudaGetSymbolAddress((void**)&pbs, g_bsums);

    cudaFuncSetAttribute(gemm1_kernel,
                         cudaFuncAttributeMaxDynamicSharedMemorySize, SMEM_MMA);
    cudaFuncSetAttribute(gemm_mid_kernel,
                         cudaFuncAttributeMaxDynamicSharedMemorySize, SMEM_MMA);

    const int nblk_scan = (N + SCAN_BLK - 1) / SCAN_BLK;
    const int gemm_grid = (N + 127) / 128;
    const int gather_blocks = (int)(((long long)N * 32 + 255) / 256);

    // --- fork: norm+CSR build on side stream; convertW + GEMM1 on main ---
    cudaStream_t sB;
    cudaStreamCreateWithFlags(&sB, cudaStreamNonBlocking);
    cudaEvent_t evFork, evNorms, evJoin;
    cudaEventCreateWithFlags(&evFork,  cudaEventDisableTiming);
    cudaEventCreateWithFlags(&evNorms, cudaEventDisableTiming);
    cudaEventCreateWithFlags(&evJoin,  cudaEventDisableTiming);

    cudaEventRecord(evFork, 0);
    cudaStreamWaitEvent(sB, evFork, 0);

    zero_deg_kernel<<<(N + 255) / 256, 256, 0, sB>>>(pod, pid_, N);
    count_deg_kernel<<<(E + 255) / 256, 256, 0, sB>>>(src, dst, pod, pid_, E);
    norms_kernel<<<(N + 255) / 256, 256, 0, sB>>>(pod, pid_, pns, pnd, N);
    cudaEventRecord(evNorms, sB);
    blocksum_kernel<<<nblk_scan, SCAN_BLK, 0, sB>>>(pid_, pbs, N);
    scan_bsums_kernel<<<1, MAX_BLKS, 0, sB>>>(pbs, nblk_scan);
    write_offsets_kernel<<<nblk_scan, SCAN_BLK, 0, sB>>>(pid_, pbs, poff, pcur, N);
    fill_csr_kernel<<<(E + 255) / 256, 256, 0, sB>>>(src, dst, pcur, pcsr, E);
    zero_out_kernel<<<(out_size + 255) / 256, 256, 0, sB>>>(out, out_size);
    cudaEventRecord(evJoin, sB);

    // main: convertW, GEMM1 (waits only on norms for its rowscale epilogue)
    convertW_kernel<<<(3 * HDIM * HDIM + 255) / 256, 256>>>(W1, W2, W3, pWhi, pWlo);
    cudaStreamWaitEvent(0, evNorms, 0);
    gemm1_kernel<<<gemm_grid, 512, SMEM_MMA>>>(node_feats, pWhi, pWlo, pns, pV, N);

    cudaStreamWaitEvent(0, evJoin, 0);   // gathers need CSR

    // --- layer 1: gather (clean) -> GEMM2 (ns epilogue) ---
    gather_u_kernel<<<gather_blocks, 256>>>(pV, poff, pid_, pcsr, pnd, b1,
                                            puhi, pulo, N);
    gemm_mid_kernel<<<gemm_grid, 512, SMEM_MMA>>>(puhi, pulo,
        pWhi + HDIM * HDIM, pWlo + HDIM * HDIM, pns, pV, N);

    // --- layer 2: gather -> GEMM3 ---
    gather_u_kernel<<<gather_blocks, 256>>>(pV, poff, pid_, pcsr, pnd, b2,
                                            puhi, pulo, N);
    gemm_mid_kernel<<<gemm_grid, 512, SMEM_MMA>>>(puhi, pulo,
        pWhi + 2 * HDIM * HDIM, pWlo + 2 * HDIM * HDIM, pns, pV, N);

    // --- final gather (fp32 h) + pool ---
    gather_final_kernel<<<gather_blocks, 256>>>(pV, poff, pid_, pcsr,
                                                pnd, b3, phA, N);
    pool_kernel<<<NUM_GRAPHS * POOL_SPLIT, HDIM>>>(phA, gid, Wp, bp, out, N);
    // single side stream + 3 events, not destroyed (capture safety)
}

// round 11
// speedup vs baseline: 1.2856x; 1.1385x over previous
#include <cuda_runtime.h>
#include <cuda_bf16.h>
#include <cuda_fp16.h>
#include <mma.h>
#include <math.h>
#include <stdint.h>

using namespace nvcuda;

#define HDIM 128
#define MAXN 100000
#define MAXE 1600000
#define POOL_SPLIT 8
#define NUM_GRAPHS 100
#define SCAN_BLK 256
#define MAX_BLKS 512

// smem layout (bytes). ldm = 136 bf16 (272B rows)
#define LDA 136
#define SA_HI 0
#define SA_LO (128 * LDA * 2)
#define SB_HI (2 * 128 * LDA * 2)
#define SB_LO (3 * 128 * LDA * 2)
#define SMEM_MMA (4 * 128 * LDA * 2)   // 139264 bytes

// ---------------- scratch (no allocation allowed) ----------------
__device__ __half g_Y[MAXN * HDIM];                // Z (GEMM output, fp16)
__device__ float g_hA[MAXN * HDIM];                // final h (fp32, for pool)
__device__ __nv_bfloat16 g_uhi[MAXN * HDIM];       // GEMM input hi
__device__ __nv_bfloat16 g_ulo[MAXN * HDIM];       // GEMM input lo
__device__ __nv_bfloat16 g_Whi[3 * HDIM * HDIM];   // W hi  [k][n]
__device__ __nv_bfloat16 g_Wlo[3 * HDIM * HDIM];   // W lo  [k][n]
__device__ float g_ns[MAXN];
__device__ float g_nd[MAXN];
__device__ int   g_odeg[MAXN];
__device__ int   g_ideg[MAXN];
__device__ int   g_off[MAXN];
__device__ int   g_cursor[MAXN];
__device__ int   g_csr_src[MAXE];
__device__ int   g_bsums[MAX_BLKS];

// ---------------- degree counting ----------------
__global__ void zero_deg_kernel(int* odeg, int* ideg, int N) {
    int i = blockIdx.x * blockDim.x + threadIdx.x;
    if (i < N) { odeg[i] = 0; ideg[i] = 0; }
}

__global__ void count_deg_kernel(const int* __restrict__ src,
                                 const int* __restrict__ dst,
                                 int* odeg, int* ideg, int E) {
    int i = blockIdx.x * blockDim.x + threadIdx.x;
    if (i < E) {
        atomicAdd(&odeg[src[i]], 1);
        atomicAdd(&ideg[dst[i]], 1);
    }
}

__global__ void norms_kernel(const int* __restrict__ odeg,
                             const int* __restrict__ ideg,
                             float* ns, float* nd, int N) {
    int i = blockIdx.x * blockDim.x + threadIdx.x;
    if (i < N) {
        ns[i] = rsqrtf((float)(odeg[i] + 1));
        nd[i] = rsqrtf((float)(ideg[i] + 1));
    }
}

// ---------------- prefix sum ----------------
__global__ void blocksum_kernel(const int* __restrict__ deg, int* bsums, int N) {
    __shared__ int s[SCAN_BLK];
    int i = blockIdx.x * SCAN_BLK + threadIdx.x;
    s[threadIdx.x] = (i < N) ? deg[i] : 0;
    __syncthreads();
    for (int o = SCAN_BLK / 2; o > 0; o >>= 1) {
        if (threadIdx.x < o) s[threadIdx.x] += s[threadIdx.x + o];
        __syncthreads();
    }
    if (threadIdx.x == 0) bsums[blockIdx.x] = s[0];
}

__global__ void scan_bsums_kernel(int* bsums, int nblk) {
    __shared__ int s[MAX_BLKS];
    int t = threadIdx.x;
    int v = (t < nblk) ? bsums[t] : 0;
    s[t] = v;
    __syncthreads();
    for (int o = 1; o < MAX_BLKS; o <<= 1) {
        int add = (t >= o) ? s[t - o] : 0;
        __syncthreads();
        s[t] += add;
        __syncthreads();
    }
    if (t < nblk) bsums[t] = s[t] - v;
}

__global__ void write_offsets_kernel(const int* __restrict__ deg,
                                     const int* __restrict__ bsums,
                                     int* off, int* cursor, int N) {
    __shared__ int s[SCAN_BLK];
    int i = blockIdx.x * SCAN_BLK + threadIdx.x;
    int t = threadIdx.x;
    int v = (i < N) ? deg[i] : 0;
    s[t] = v;
    __syncthreads();
    for (int o = 1; o < SCAN_BLK; o <<= 1) {
        int add = (t >= o) ? s[t - o] : 0;
        __syncthreads();
        s[t] += add;
        __syncthreads();
    }
    if (i < N) {
        int ofs = bsums[blockIdx.x] + s[t] - v;
        off[i] = ofs;
        cursor[i] = ofs;
    }
}

__global__ void fill_csr_kernel(const int* __restrict__ src,
                                const int* __restrict__ dst,
                                int* cursor, int* csr_src, int E) {
    int i = blockIdx.x * blockDim.x + threadIdx.x;
    if (i < E) {
        int slot = atomicAdd(&cursor[dst[i]], 1);
        csr_src[slot] = src[i];
    }
}

// ---------------- convert W: hi/lo split ----------------
__global__ void convertW_kernel(const float* __restrict__ W1,
                                const float* __restrict__ W2,
                                const float* __restrict__ W3,
                                __nv_bfloat16* __restrict__ Whi,
                                __nv_bfloat16* __restrict__ Wlo) {
    int i = blockIdx.x * blockDim.x + threadIdx.x;
    if (i >= 3 * HDIM * HDIM) return;
    int w = i / (HDIM * HDIM);
    int r = i % (HDIM * HDIM);
    const float* W = (w == 0) ? W1 : ((w == 1) ? W2 : W3);
    float v = W[r];
    __nv_bfloat16 hi = __float2bfloat16(v);
    Whi[i] = hi;
    Wlo[i] = __float2bfloat16(v - __bfloat162float(hi));
}

// ---------------- convert X (fp32 -> bf16 hi/lo) ----------------
__global__ void convertX_kernel(const float* __restrict__ X,
                                __nv_bfloat16* __restrict__ Xhi,
                                __nv_bfloat16* __restrict__ Xlo, int n4) {
    int i = blockIdx.x * blockDim.x + threadIdx.x;
    if (i >= n4) return;
    float4 v = ((const float4*)X)[i];
    __nv_bfloat16 h0 = __float2bfloat16(v.x);
    __nv_bfloat16 h1 = __float2bfloat16(v.y);
    __nv_bfloat16 h2 = __float2bfloat16(v.z);
    __nv_bfloat16 h3 = __float2bfloat16(v.w);
    __nv_bfloat162* XH = (__nv_bfloat162*)Xhi;
    __nv_bfloat162* XL = (__nv_bfloat162*)Xlo;
    XH[i * 2 + 0] = __halves2bfloat162(h0, h1);
    XH[i * 2 + 1] = __halves2bfloat162(h2, h3);
    XL[i * 2 + 0] = __halves2bfloat162(
        __float2bfloat16(v.x - __bfloat162float(h0)),
        __float2bfloat16(v.y - __bfloat162float(h1)));
    XL[i * 2 + 1] = __halves2bfloat162(
        __float2bfloat16(v.z - __bfloat162float(h2)),
        __float2bfloat16(v.w - __bfloat162float(h3)));
}

// ---------------- wmma split-bf16 GEMM, fp16 output ----------------
// Z[m][n] = sum_k A[m][k]*W[k][n], A=Ahi+Alo, W=Whi+Wlo (drop lo*lo).
// CTA: 128x128 tile, 512 threads = 16 warps (4x4), warp tile 32x32.
__global__ void __launch_bounds__(512)
mma_gemm_kernel(const __nv_bfloat16* __restrict__ Ahi,
                const __nv_bfloat16* __restrict__ Alo,
                const __nv_bfloat16* __restrict__ Whi,
                const __nv_bfloat16* __restrict__ Wlo,
                __half* __restrict__ Y, int N) {
    extern __shared__ char smem[];
    __nv_bfloat16* sAhi = (__nv_bfloat16*)(smem + SA_HI);
    __nv_bfloat16* sAlo = (__nv_bfloat16*)(smem + SA_LO);
    __nv_bfloat16* sBhi = (__nv_bfloat16*)(smem + SB_HI);
    __nv_bfloat16* sBlo = (__nv_bfloat16*)(smem + SB_LO);

    const int tid = threadIdx.x;
    const int base = blockIdx.x * 128;

    const uint4* WH4 = (const uint4*)Whi;
    const uint4* WL4 = (const uint4*)Wlo;
    const uint4* AH4 = (const uint4*)Ahi;
    const uint4* AL4 = (const uint4*)Alo;
    const uint4 z4 = make_uint4(0, 0, 0, 0);
    #pragma unroll
    for (int i = tid; i < 128 * 16; i += 512) {
        int row = i >> 4, c8 = i & 15;
        int gr = base + row;
        bool ok = gr < N;
        *(uint4*)&sAhi[row * LDA + c8 * 8] = ok ? AH4[(size_t)gr * 16 + c8] : z4;
        *(uint4*)&sAlo[row * LDA + c8 * 8] = ok ? AL4[(size_t)gr * 16 + c8] : z4;
        *(uint4*)&sBhi[row * LDA + c8 * 8] = WH4[i];
        *(uint4*)&sBlo[row * LDA + c8 * 8] = WL4[i];
    }
    __syncthreads();

    const int wid = tid >> 5;
    const int wm = wid & 3;
    const int wn = wid >> 2;

    wmma::fragment<wmma::accumulator, 16, 16, 16, float> acc[2][2];
    #pragma unroll
    for (int i = 0; i < 2; i++)
        #pragma unroll
        for (int j = 0; j < 2; j++)
            wmma::fill_fragment(acc[i][j], 0.0f);

    #pragma unroll
    for (int ks = 0; ks < 8; ks++) {
        wmma::fragment<wmma::matrix_a, 16, 16, 16, __nv_bfloat16, wmma::row_major> ahi[2], alo[2];
        wmma::fragment<wmma::matrix_b, 16, 16, 16, __nv_bfloat16, wmma::row_major> bhi[2], blo[2];
        #pragma unroll
        for (int i = 0; i < 2; i++) {
            wmma::load_matrix_sync(ahi[i], &sAhi[(wm * 32 + i * 16) * LDA + ks * 16], LDA);
            wmma::load_matrix_sync(alo[i], &sAlo[(wm * 32 + i * 16) * LDA + ks * 16], LDA);
        }
        #pragma unroll
        for (int j = 0; j < 2; j++) {
            wmma::load_matrix_sync(bhi[j], &sBhi[(ks * 16) * LDA + wn * 32 + j * 16], LDA);
            wmma::load_matrix_sync(blo[j], &sBlo[(ks * 16) * LDA + wn * 32 + j * 16], LDA);
        }
        #pragma unroll
        for (int i = 0; i < 2; i++)
            #pragma unroll
            for (int j = 0; j < 2; j++) {
                wmma::mma_sync(acc[i][j], ahi[i], bhi[j], acc[i][j]);
                wmma::mma_sync(acc[i][j], ahi[i], blo[j], acc[i][j]);
                wmma::mma_sync(acc[i][j], alo[i], bhi[j], acc[i][j]);
            }
    }

    // stage via smem (aliases sA/sB; wmma loads done), convert to fp16
    __syncthreads();
    float* fs = (float*)smem;   // 64 KB
    #pragma unroll
    for (int i = 0; i < 2; i++)
        #pragma unroll
        for (int j = 0; j < 2; j++)
            wmma::store_matrix_sync(
                fs + (wm * 32 + i * 16) * HDIM + wn * 32 + j * 16,
                acc[i][j], HDIM, wmma::mem_row_major);
    __syncthreads();
    uint2* Y2 = (uint2*)Y;
    const float4* fs4 = (const float4*)fs;
    #pragma unroll
    for (int i = tid; i < 128 * 32; i += 512) {
        int row = i >> 5;
        int gr = base + row;
        if (gr < N) {
            float4 v = fs4[i];
            __half2 p0 = __floats2half2_rn(v.x, v.y);
            __half2 p1 = __floats2half2_rn(v.z, v.w);
            uint2 u;
            u.x = *(uint32_t*)&p0;
            u.y = *(uint32_t*)&p1;
            Y2[(size_t)gr * 32 + (i & 31)] = u;
        }
    }
}

// ---------------- fp16 row-chunk load: 4 dims per lane ----------------
__device__ __forceinline__ float4 ldY4(const uint2* __restrict__ Y2,
                                       int n, int lane) {
    uint2 u = __ldg(&Y2[(size_t)n * 32 + lane]);
    __half2 a = *(__half2*)&u.x;
    __half2 b = *(__half2*)&u.y;
    float2 fa = __half22float2(a);
    float2 fb = __half22float2(b);
    return make_float4(fa.x, fa.y, fb.x, fb.y);
}

// ---------------- fused gather + epilogue + next-layer input prep ----------
// mode 0: per-edge ns (layer 1), out u=ns*h bf16 hi/lo
// mode 1: pre-scaled input, out u bf16 hi/lo
// mode 2: pre-scaled input, out h fp32 (final)
__global__ void gather_kernel(const __half* __restrict__ Z,
                              const int* __restrict__ off,
                              const int* __restrict__ ideg,
                              const int* __restrict__ csr_src,
                              const float* __restrict__ ns,
                              const float* __restrict__ nd,
                              const float* __restrict__ b,
                              __nv_bfloat16* __restrict__ uhi,
                              __nv_bfloat16* __restrict__ ulo,
                              float* __restrict__ hout,
                              int mode, int N) {
    int gt = blockIdx.x * blockDim.x + threadIdx.x;
    int n = gt >> 5;
    int lane = threadIdx.x & 31;
    if (n >= N) return;

    const uint2* Z2 = (const uint2*)Z;
    float4 acc = ldY4(Z2, n, lane);
    if (mode == 0) {
        float sn = ns[n];
        acc.x *= sn; acc.y *= sn; acc.z *= sn; acc.w *= sn;
    }
    int o = off[n];
    int d = ideg[n];

    int e = 0;
    if (mode == 0) {
        for (; e + 4 <= d; e += 4) {
            int s0 = csr_src[o + e + 0];
            int s1 = csr_src[o + e + 1];
            int s2 = csr_src[o + e + 2];
            int s3 = csr_src[o + e + 3];
            float n0 = __ldg(&ns[s0]);
            float n1 = __ldg(&ns[s1]);
            float n2 = __ldg(&ns[s2]);
            float n3 = __ldg(&ns[s3]);
            float4 v0 = ldY4(Z2, s0, lane);
            float4 v1 = ldY4(Z2, s1, lane);
            float4 v2 = ldY4(Z2, s2, lane);
            float4 v3 = ldY4(Z2, s3, lane);
            acc.x += v0.x * n0 + v1.x * n1 + v2.x * n2 + v3.x * n3;
            acc.y += v0.y * n0 + v1.y * n1 + v2.y * n2 + v3.y * n3;
            acc.z += v0.z * n0 + v1.z * n1 + v2.z * n2 + v3.z * n3;
            acc.w += v0.w * n0 + v1.w * n1 + v2.w * n2 + v3.w * n3;
        }
        for (; e < d; e++) {
            int s = csr_src[o + e];
            float nn = __ldg(&ns[s]);
            float4 v = ldY4(Z2, s, lane);
            acc.x += v.x * nn; acc.y += v.y * nn;
            acc.z += v.z * nn; acc.w += v.w * nn;
        }
    } else {
        for (; e + 4 <= d; e += 4) {
            int s0 = csr_src[o + e + 0];
            int s1 = csr_src[o + e + 1];
            int s2 = csr_src[o + e + 2];
            int s3 = csr_src[o + e + 3];
            float4 v0 = ldY4(Z2, s0, lane);
            float4 v1 = ldY4(Z2, s1, lane);
            float4 v2 = ldY4(Z2, s2, lane);
            float4 v3 = ldY4(Z2, s3, lane);
            acc.x += v0.x + v1.x + v2.x + v3.x;
            acc.y += v0.y + v1.y + v2.y + v3.y;
            acc.z += v0.z + v1.z + v2.z + v3.z;
            acc.w += v0.w + v1.w + v2.w + v3.w;
        }
        for (; e < d; e++) {
            int s = csr_src[o + e];
            float4 v = ldY4(Z2, s, lane);
            acc.x += v.x; acc.y += v.y; acc.z += v.z; acc.w += v.w;
        }
    }

    float sc = nd[n];
    float4 bb = ((const float4*)b)[lane];
    float hx = fmaxf(acc.x * sc + bb.x, 0.f);
    float hy = fmaxf(acc.y * sc + bb.y, 0.f);
    float hz = fmaxf(acc.z * sc + bb.z, 0.f);
    float hw = fmaxf(acc.w * sc + bb.w, 0.f);

    if (mode < 2) {
        float un = ns[n];
        float ux = hx * un, uy = hy * un, uz = hz * un, uw = hw * un;
        __nv_bfloat16 h0 = __float2bfloat16(ux);
        __nv_bfloat16 h1 = __float2bfloat16(uy);
        __nv_bfloat16 h2 = __float2bfloat16(uz);
        __nv_bfloat16 h3 = __float2bfloat16(uw);
        __nv_bfloat162* UH = (__nv_bfloat162*)uhi;
        __nv_bfloat162* UL = (__nv_bfloat162*)ulo;
        size_t i2 = (size_t)n * 64 + lane * 2;
        UH[i2 + 0] = __halves2bfloat162(h0, h1);
        UH[i2 + 1] = __halves2bfloat162(h2, h3);
        UL[i2 + 0] = __halves2bfloat162(
            __float2bfloat16(ux - __bfloat162float(h0)),
            __float2bfloat16(uy - __bfloat162float(h1)));
        UL[i2 + 1] = __halves2bfloat162(
            __float2bfloat16(uz - __bfloat162float(h2)),
            __float2bfloat16(uw - __bfloat162float(h3)));
    } else {
        ((float4*)hout)[(size_t)n * 32 + lane] = make_float4(hx, hy, hz, hw);
    }
}

// ---------------- output zero init ----------------
__global__ void zero_out_kernel(float* out, int n) {
    int i = blockIdx.x * blockDim.x + threadIdx.x;
    if (i < n) out[i] = 0.f;
}

// ---------------- pooling ----------------
__global__ void pool_kernel(const float* __restrict__ h,
                            const int* __restrict__ gid,
                            const float* __restrict__ Wp,
                            const float* __restrict__ bp,
                            float* __restrict__ out, int N) {
    const int g    = blockIdx.x / POOL_SPLIT;
    const int part = blockIdx.x % POOL_SPLIT;
    const int tid  = threadIdx.x;

    int lo = 0, hi = N;
    while (lo < hi) { int m = (lo + hi) >> 1; if (gid[m] < g) lo = m + 1; else hi = m; }
    int start = lo;
    lo = start; hi = N;
    while (lo < hi) { int m = (lo + hi) >> 1; if (gid[m] < g + 1) lo = m + 1; else hi = m; }
    int end = lo;

    __shared__ float sWp[HDIM];
    __shared__ float red[4];
    __shared__ float sdot;
    sWp[tid] = Wp[tid];
    float bpv = bp[0];
    __syncthreads();

    float lsum = 0.f;
    float lmax = 0.f;
    const int lane = tid & 31;
    const int warp = tid >> 5;

    for (int n = start + part; n < end; n += POOL_SPLIT) {
        float val = h[n * HDIM + tid];
        float p = val * sWp[tid];
        #pragma unroll
        for (int o = 16; o > 0; o >>= 1)
            p += __shfl_down_sync(0xFFFFFFFFu, p, o);
        if (lane == 0) red[warp] = p;
        __syncthreads();
        if (tid == 0) sdot = red[0] + red[1] + red[2] + red[3] + bpv;
        __syncthreads();
        float w = 1.0f / (1.0f + expf(-sdot));
        lsum += val * w;
        lmax = fmaxf(lmax, val);
        __syncthreads();
    }

    if (end > start) {
        atomicAdd(&out[g * 2 * HDIM + tid], lsum);
        atomicMax((int*)&out[g * 2 * HDIM + HDIM + tid], __float_as_int(lmax));
    }
}

// ---------------- launch ----------------
extern "C" void kernel_launch(void* const* d_in, const int* in_sizes, int n_in,
                              void* d_out, int out_size) {
    const float* node_feats = (const float*)d_in[0];
    const int*   src        = (const int*)d_in[1];
    const int*   dst        = (const int*)d_in[2];
    const int*   gid        = (const int*)d_in[3];
    const float* W1 = (const float*)d_in[4];  const float* b1 = (const float*)d_in[5];
    const float* W2 = (const float*)d_in[6];  const float* b2 = (const float*)d_in[7];
    const float* W3 = (const float*)d_in[8];  const float* b3 = (const float*)d_in[9];
    const float* Wp = (const float*)d_in[10]; const float* bp = (const float*)d_in[11];
    float* out = (float*)d_out;

    const int N = in_sizes[0] / HDIM;
    const int E = in_sizes[1];

    float *phA, *pns, *pnd;
    __half* pY;
    __nv_bfloat16 *puhi, *pulo, *pWhi, *pWlo;
    int *pod, *pid_, *poff, *pcur, *pcsr, *pbs;
    cudaGetSymbolAddress((void**)&pY,   g_Y);
    cudaGetSymbolAddress((void**)&phA,  g_hA);
    cudaGetSymbolAddress((void**)&puhi, g_uhi);
    cudaGetSymbolAddress((void**)&pulo, g_ulo);
    cudaGetSymbolAddress((void**)&pWhi, g_Whi);
    cudaGetSymbolAddress((void**)&pWlo, g_Wlo);
    cudaGetSymbolAddress((void**)&pns, g_ns);
    cudaGetSymbolAddress((void**)&pnd, g_nd);
    cudaGetSymbolAddress((void**)&pod, g_odeg);
    cudaGetSymbolAddress((void**)&pid_, g_ideg);
    cudaGetSymbolAddress((void**)&poff, g_off);
    cudaGetSymbolAddress((void**)&pcur, g_cursor);
    cudaGetSymbolAddress((void**)&pcsr, g_csr_src);
    cudaGetSymbolAddress((void**)&pbs, g_bsums);

    cudaFuncSetAttribute(mma_gemm_kernel,
                         cudaFuncAttributeMaxDynamicSharedMemorySize, SMEM_MMA);

    const int nblk_scan = (N + SCAN_BLK - 1) / SCAN_BLK;
    const int gemm_grid = (N + 127) / 128;
    const int gather_blocks = (int)(((long long)N * 32 + 255) / 256);

    // --- fork: CSR/norm build on side stream; conversions + GEMM1 on main ---
    cudaStream_t sB;
    cudaStreamCreateWithFlags(&sB, cudaStreamNonBlocking);
    cudaEvent_t evFork, evJoin;
    cudaEventCreateWithFlags(&evFork, cudaEventDisableTiming);
    cudaEventCreateWithFlags(&evJoin, cudaEventDisableTiming);

    cudaEventRecord(evFork, 0);
    cudaStreamWaitEvent(sB, evFork, 0);

    zero_deg_kernel<<<(N + 255) / 256, 256, 0, sB>>>(pod, pid_, N);
    count_deg_kernel<<<(E + 255) / 256, 256, 0, sB>>>(src, dst, pod, pid_, E);
    norms_kernel<<<(N + 255) / 256, 256, 0, sB>>>(pod, pid_, pns, pnd, N);
    blocksum_kernel<<<nblk_scan, SCAN_BLK, 0, sB>>>(pid_, pbs, N);
    scan_bsums_kernel<<<1, MAX_BLKS, 0, sB>>>(pbs, nblk_scan);
    write_offsets_kernel<<<nblk_scan, SCAN_BLK, 0, sB>>>(pid_, pbs, poff, pcur, N);
    fill_csr_kernel<<<(E + 255) / 256, 256, 0, sB>>>(src, dst, pcur, pcsr, E);
    zero_out_kernel<<<(out_size + 255) / 256, 256, 0, sB>>>(out, out_size);

    // main: W + X conversion, GEMM1 (independent of norms/CSR)
    convertW_kernel<<<(3 * HDIM * HDIM + 255) / 256, 256>>>(W1, W2, W3, pWhi, pWlo);
    convertX_kernel<<<(N * 32 + 255) / 256, 256>>>(node_feats, puhi, pulo, N * 32);
    mma_gemm_kernel<<<gemm_grid, 512, SMEM_MMA>>>(puhi, pulo, pWhi, pWlo, pY, N);

    cudaEventRecord(evJoin, sB);
    cudaStreamWaitEvent(0, evJoin, 0);

    // --- layer 1 gather (per-edge ns), then layers 2-3 ---
    gather_kernel<<<gather_blocks, 256>>>(pY, poff, pid_, pcsr, pns, pnd, b1,
                                          puhi, pulo, phA, 0, N);
    mma_gemm_kernel<<<gemm_grid, 512, SMEM_MMA>>>(puhi, pulo,
                                                  pWhi + HDIM * HDIM,
                                                  pWlo + HDIM * HDIM, pY, N);
    gather_kernel<<<gather_blocks, 256>>>(pY, poff, pid_, pcsr, pns, pnd, b2,
                                          puhi, pulo, phA, 1, N);
    mma_gemm_kernel<<<gemm_grid, 512, SMEM_MMA>>>(puhi, pulo,
                                                  pWhi + 2 * HDIM * HDIM,
                                                  pWlo + 2 * HDIM * HDIM, pY, N);
    gather_kernel<<<gather_blocks, 256>>>(pY, poff, pid_, pcsr, pns, pnd, b3,
                                          puhi, pulo, phA, 2, N);

    pool_kernel<<<NUM_GRAPHS * POOL_SPLIT, HDIM>>>(phA, gid, Wp, bp, out, N);
    // single side stream + 2 events, not destroyed (round-6-proven pattern)
}

// round 12
// speedup vs baseline: 1.5990x; 1.2437x over previous
#include <cuda_runtime.h>
#include <cuda_bf16.h>
#include <cuda_fp16.h>
#include <mma.h>
#include <math.h>
#include <stdint.h>

using namespace nvcuda;

#define HDIM 128
#define MAXN 100000
#define MAXE 1600000
#define NUM_GRAPHS 100
#define SCAN_BLK 256
#define MAX_BLKS 512

// smem layout (bytes). ldm = 136 bf16 (272B rows)
#define LDA 136
#define SA_HI 0
#define SA_LO (128 * LDA * 2)
#define SB_HI (2 * 128 * LDA * 2)
#define SB_LO (3 * 128 * LDA * 2)
#define SMEM_MMA (4 * 128 * LDA * 2)   // 139264 bytes

// ---------------- scratch (no allocation allowed) ----------------
__device__ __half g_Y[MAXN * HDIM];                // Z (GEMM output, fp16)
__device__ __half g_u[MAXN * HDIM];                // u = ns*h (GEMM input, fp16)
__device__ float g_hA[MAXN * HDIM];                // final h (fp32, for pool)
__device__ __nv_bfloat16 g_Whi[3 * HDIM * HDIM];   // W hi  [k][n]
__device__ __nv_bfloat16 g_Wlo[3 * HDIM * HDIM];   // W lo  [k][n]
__device__ float g_ns[MAXN];
__device__ float g_nd[MAXN];
__device__ int   g_odeg[MAXN];
__device__ int   g_ideg[MAXN];
__device__ int   g_off[MAXN];
__device__ int   g_cursor[MAXN];
__device__ int   g_csr_src[MAXE];
__device__ int   g_bsums[MAX_BLKS];

// ---------------- degree counting ----------------
__global__ void zero_deg_kernel(int* odeg, int* ideg, int N) {
    int i = blockIdx.x * blockDim.x + threadIdx.x;
    if (i < N) { odeg[i] = 0; ideg[i] = 0; }
}

__global__ void count_deg_kernel(const int* __restrict__ src,
                                 const int* __restrict__ dst,
                                 int* odeg, int* ideg, int E) {
    int i = blockIdx.x * blockDim.x + threadIdx.x;
    if (i < E) {
        atomicAdd(&odeg[src[i]], 1);
        atomicAdd(&ideg[dst[i]], 1);
    }
}

__global__ void norms_kernel(const int* __restrict__ odeg,
                             const int* __restrict__ ideg,
                             float* ns, float* nd, int N) {
    int i = blockIdx.x * blockDim.x + threadIdx.x;
    if (i < N) {
        ns[i] = rsqrtf((float)(odeg[i] + 1));
        nd[i] = rsqrtf((float)(ideg[i] + 1));
    }
}

// ---------------- prefix sum ----------------
__global__ void blocksum_kernel(const int* __restrict__ deg, int* bsums, int N) {
    __shared__ int s[SCAN_BLK];
    int i = blockIdx.x * SCAN_BLK + threadIdx.x;
    s[threadIdx.x] = (i < N) ? deg[i] : 0;
    __syncthreads();
    for (int o = SCAN_BLK / 2; o > 0; o >>= 1) {
        if (threadIdx.x < o) s[threadIdx.x] += s[threadIdx.x + o];
        __syncthreads();
    }
    if (threadIdx.x == 0) bsums[blockIdx.x] = s[0];
}

__global__ void scan_bsums_kernel(int* bsums, int nblk) {
    __shared__ int s[MAX_BLKS];
    int t = threadIdx.x;
    int v = (t < nblk) ? bsums[t] : 0;
    s[t] = v;
    __syncthreads();
    for (int o = 1; o < MAX_BLKS; o <<= 1) {
        int add = (t >= o) ? s[t - o] : 0;
        __syncthreads();
        s[t] += add;
        __syncthreads();
    }
    if (t < nblk) bsums[t] = s[t] - v;
}

__global__ void write_offsets_kernel(const int* __restrict__ deg,
                                     const int* __restrict__ bsums,
                                     int* off, int* cursor, int N) {
    __shared__ int s[SCAN_BLK];
    int i = blockIdx.x * SCAN_BLK + threadIdx.x;
    int t = threadIdx.x;
    int v = (i < N) ? deg[i] : 0;
    s[t] = v;
    __syncthreads();
    for (int o = 1; o < SCAN_BLK; o <<= 1) {
        int add = (t >= o) ? s[t - o] : 0;
        __syncthreads();
        s[t] += add;
        __syncthreads();
    }
    if (i < N) {
        int ofs = bsums[blockIdx.x] + s[t] - v;
        off[i] = ofs;
        cursor[i] = ofs;
    }
}

__global__ void fill_csr_kernel(const int* __restrict__ src,
                                const int* __restrict__ dst,
                                int* cursor, int* csr_src, int E) {
    int i = blockIdx.x * blockDim.x + threadIdx.x;
    if (i < E) {
        int slot = atomicAdd(&cursor[dst[i]], 1);
        csr_src[slot] = src[i];
    }
}

// ---------------- convert W: hi/lo split ----------------
__global__ void convertW_kernel(const float* __restrict__ W1,
                                const float* __restrict__ W2,
                                const float* __restrict__ W3,
                                __nv_bfloat16* __restrict__ Whi,
                                __nv_bfloat16* __restrict__ Wlo) {
    int i = blockIdx.x * blockDim.x + threadIdx.x;
    if (i >= 3 * HDIM * HDIM) return;
    int w = i / (HDIM * HDIM);
    int r = i % (HDIM * HDIM);
    const float* W = (w == 0) ? W1 : ((w == 1) ? W2 : W3);
    float v = W[r];
    __nv_bfloat16 hi = __float2bfloat16(v);
    Whi[i] = hi;
    Wlo[i] = __float2bfloat16(v - __bfloat162float(hi));
}

// ---------------- convert X (fp32 -> fp16) ----------------
__global__ void convertX_kernel(const float* __restrict__ X,
                                __half* __restrict__ Xh, int n4) {
    int i = blockIdx.x * blockDim.x + threadIdx.x;
    if (i >= n4) return;
    float4 v = ((const float4*)X)[i];
    __half2 p0 = __floats2half2_rn(v.x, v.y);
    __half2 p1 = __floats2half2_rn(v.z, v.w);
    uint2 u;
    u.x = *(uint32_t*)&p0;
    u.y = *(uint32_t*)&p1;
    ((uint2*)Xh)[i] = u;
}

// ---------------- wmma split-bf16 GEMM: fp16 in, fp16 out ----------------
// Z[m][n] = sum_k A[m][k]*W[k][n]; A fp16 split -> bf16 hi/lo in staging
// (lossless: 16 mantissa bits >= fp16's 11). W = Whi+Wlo (drop lo*lo).
__global__ void __launch_bounds__(512)
mma_gemm_kernel(const __half* __restrict__ A,
                const __nv_bfloat16* __restrict__ Whi,
                const __nv_bfloat16* __restrict__ Wlo,
                __half* __restrict__ Y, int N) {
    extern __shared__ char smem[];
    __nv_bfloat16* sAhi = (__nv_bfloat16*)(smem + SA_HI);
    __nv_bfloat16* sAlo = (__nv_bfloat16*)(smem + SA_LO);
    __nv_bfloat16* sBhi = (__nv_bfloat16*)(smem + SB_HI);
    __nv_bfloat16* sBlo = (__nv_bfloat16*)(smem + SB_LO);

    const int tid = threadIdx.x;
    const int base = blockIdx.x * 128;

    const uint4* WH4 = (const uint4*)Whi;
    const uint4* WL4 = (const uint4*)Wlo;
    const uint4* A4 = (const uint4*)A;     // 16 uint4 (8 halves each) per row
    const uint4 z4 = make_uint4(0, 0, 0, 0);
    #pragma unroll
    for (int i = tid; i < 128 * 16; i += 512) {
        int row = i >> 4, c8 = i & 15;
        int gr = base + row;
        uint4 a = (gr < N) ? A4[(size_t)gr * 16 + c8] : z4;
        const __half2* hp = (const __half2*)&a;
        uint32_t hiw[4], low[4];
        #pragma unroll
        for (int j = 0; j < 4; j++) {
            float2 f = __half22float2(hp[j]);
            __nv_bfloat16 b0 = __float2bfloat16(f.x);
            __nv_bfloat16 b1 = __float2bfloat16(f.y);
            __nv_bfloat162 bh = __halves2bfloat162(b0, b1);
            __nv_bfloat162 bl = __halves2bfloat162(
                __float2bfloat16(f.x - __bfloat162float(b0)),
                __float2bfloat16(f.y - __bfloat162float(b1)));
            hiw[j] = *(uint32_t*)&bh;
            low[j] = *(uint32_t*)&bl;
        }
        *(uint4*)&sAhi[row * LDA + c8 * 8] = make_uint4(hiw[0], hiw[1], hiw[2], hiw[3]);
        *(uint4*)&sAlo[row * LDA + c8 * 8] = make_uint4(low[0], low[1], low[2], low[3]);
        *(uint4*)&sBhi[row * LDA + c8 * 8] = WH4[i];
        *(uint4*)&sBlo[row * LDA + c8 * 8] = WL4[i];
    }
    __syncthreads();

    const int wid = tid >> 5;
    const int wm = wid & 3;
    const int wn = wid >> 2;

    wmma::fragment<wmma::accumulator, 16, 16, 16, float> acc[2][2];
    #pragma unroll
    for (int i = 0; i < 2; i++)
        #pragma unroll
        for (int j = 0; j < 2; j++)
            wmma::fill_fragment(acc[i][j], 0.0f);

    #pragma unroll
    for (int ks = 0; ks < 8; ks++) {
        wmma::fragment<wmma::matrix_a, 16, 16, 16, __nv_bfloat16, wmma::row_major> ahi[2], alo[2];
        wmma::fragment<wmma::matrix_b, 16, 16, 16, __nv_bfloat16, wmma::row_major> bhi[2], blo[2];
        #pragma unroll
        for (int i = 0; i < 2; i++) {
            wmma::load_matrix_sync(ahi[i], &sAhi[(wm * 32 + i * 16) * LDA + ks * 16], LDA);
            wmma::load_matrix_sync(alo[i], &sAlo[(wm * 32 + i * 16) * LDA + ks * 16], LDA);
        }
        #pragma unroll
        for (int j = 0; j < 2; j++) {
            wmma::load_matrix_sync(bhi[j], &sBhi[(ks * 16) * LDA + wn * 32 + j * 16], LDA);
            wmma::load_matrix_sync(blo[j], &sBlo[(ks * 16) * LDA + wn * 32 + j * 16], LDA);
        }
        #pragma unroll
        for (int i = 0; i < 2; i++)
            #pragma unroll
            for (int j = 0; j < 2; j++) {
                wmma::mma_sync(acc[i][j], ahi[i], bhi[j], acc[i][j]);
                wmma::mma_sync(acc[i][j], ahi[i], blo[j], acc[i][j]);
                wmma::mma_sync(acc[i][j], alo[i], bhi[j], acc[i][j]);
            }
    }

    // stage via smem (aliases sA/sB; wmma loads done), convert to fp16
    __syncthreads();
    float* fs = (float*)smem;   // 64 KB
    #pragma unroll
    for (int i = 0; i < 2; i++)
        #pragma unroll
        for (int j = 0; j < 2; j++)
            wmma::store_matrix_sync(
                fs + (wm * 32 + i * 16) * HDIM + wn * 32 + j * 16,
                acc[i][j], HDIM, wmma::mem_row_major);
    __syncthreads();
    uint2* Y2 = (uint2*)Y;
    const float4* fs4 = (const float4*)fs;
    #pragma unroll
    for (int i = tid; i < 128 * 32; i += 512) {
        int row = i >> 5;
        int gr = base + row;
        if (gr < N) {
            float4 v = fs4[i];
            __half2 p0 = __floats2half2_rn(v.x, v.y);
            __half2 p1 = __floats2half2_rn(v.z, v.w);
            uint2 u;
            u.x = *(uint32_t*)&p0;
            u.y = *(uint32_t*)&p1;
            Y2[(size_t)gr * 32 + (i & 31)] = u;
        }
    }
}

// ---------------- fp16 row-chunk load: 4 dims per lane ----------------
__device__ __forceinline__ float4 ldY4(const uint2* __restrict__ Y2,
                                       int n, int lane) {
    uint2 u = __ldg(&Y2[(size_t)n * 32 + lane]);
    __half2 a = *(__half2*)&u.x;
    __half2 b = *(__half2*)&u.y;
    float2 fa = __half22float2(a);
    float2 fb = __half22float2(b);
    return make_float4(fa.x, fa.y, fb.x, fb.y);
}

// ---------------- fused gather + epilogue + next-layer input prep ----------
// mode 0: per-edge ns (layer 1), out u = ns*h fp16
// mode 1: pre-scaled input, out u = ns*h fp16
// mode 2: pre-scaled input, out h fp32 (final, for pool)
__global__ void gather_kernel(const __half* __restrict__ Z,
                              const int* __restrict__ off,
                              const int* __restrict__ ideg,
                              const int* __restrict__ csr_src,
                              const float* __restrict__ ns,
                              const float* __restrict__ nd,
                              const float* __restrict__ b,
                              __half* __restrict__ u,
                              float* __restrict__ hout,
                              int mode, int N) {
    int gt = blockIdx.x * blockDim.x + threadIdx.x;
    int n = gt >> 5;
    int lane = threadIdx.x & 31;
    if (n >= N) return;

    const uint2* Z2 = (const uint2*)Z;
    float4 acc = ldY4(Z2, n, lane);
    if (mode == 0) {
        float sn = ns[n];
        acc.x *= sn; acc.y *= sn; acc.z *= sn; acc.w *= sn;
    }
    int o = off[n];
    int d = ideg[n];

    int e = 0;
    if (mode == 0) {
        for (; e + 4 <= d; e += 4) {
            int s0 = csr_src[o + e + 0];
            int s1 = csr_src[o + e + 1];
            int s2 = csr_src[o + e + 2];
            int s3 = csr_src[o + e + 3];
            float n0 = __ldg(&ns[s0]);
            float n1 = __ldg(&ns[s1]);
            float n2 = __ldg(&ns[s2]);
            float n3 = __ldg(&ns[s3]);
            float4 v0 = ldY4(Z2, s0, lane);
            float4 v1 = ldY4(Z2, s1, lane);
            float4 v2 = ldY4(Z2, s2, lane);
            float4 v3 = ldY4(Z2, s3, lane);
            acc.x += v0.x * n0 + v1.x * n1 + v2.x * n2 + v3.x * n3;
            acc.y += v0.y * n0 + v1.y * n1 + v2.y * n2 + v3.y * n3;
            acc.z += v0.z * n0 + v1.z * n1 + v2.z * n2 + v3.z * n3;
            acc.w += v0.w * n0 + v1.w * n1 + v2.w * n2 + v3.w * n3;
        }
        for (; e < d; e++) {
            int s = csr_src[o + e];
            float nn = __ldg(&ns[s]);
            float4 v = ldY4(Z2, s, lane);
            acc.x += v.x * nn; acc.y += v.y * nn;
            acc.z += v.z * nn; acc.w += v.w * nn;
        }
    } else {
        for (; e + 4 <= d; e += 4) {
            int s0 = csr_src[o + e + 0];
            int s1 = csr_src[o + e + 1];
            int s2 = csr_src[o + e + 2];
            int s3 = csr_src[o + e + 3];
            float4 v0 = ldY4(Z2, s0, lane);
            float4 v1 = ldY4(Z2, s1, lane);
            float4 v2 = ldY4(Z2, s2, lane);
            float4 v3 = ldY4(Z2, s3, lane);
            acc.x += v0.x + v1.x + v2.x + v3.x;
            acc.y += v0.y + v1.y + v2.y + v3.y;
            acc.z += v0.z + v1.z + v2.z + v3.z;
            acc.w += v0.w + v1.w + v2.w + v3.w;
        }
        for (; e < d; e++) {
            int s = csr_src[o + e];
            float4 v = ldY4(Z2, s, lane);
            acc.x += v.x; acc.y += v.y; acc.z += v.z; acc.w += v.w;
        }
    }

    float sc = nd[n];
    float4 bb = ((const float4*)b)[lane];
    float hx = fmaxf(acc.x * sc + bb.x, 0.f);
    float hy = fmaxf(acc.y * sc + bb.y, 0.f);
    float hz = fmaxf(acc.z * sc + bb.z, 0.f);
    float hw = fmaxf(acc.w * sc + bb.w, 0.f);

    if (mode < 2) {
        float un = ns[n];
        __half2 p0 = __floats2half2_rn(hx * un, hy * un);
        __half2 p1 = __floats2half2_rn(hz * un, hw * un);
        uint2 uu;
        uu.x = *(uint32_t*)&p0;
        uu.y = *(uint32_t*)&p1;
        ((uint2*)u)[(size_t)n * 32 + lane] = uu;
    } else {
        ((float4*)hout)[(size_t)n * 32 + lane] = make_float4(hx, hy, hz, hw);
    }
}

// ---------------- output zero init ----------------
__global__ void zero_out_kernel(float* out, int n) {
    int i = blockIdx.x * blockDim.x + threadIdx.x;
    if (i < n) out[i] = 0.f;
}

// ---------------- pooling: warp-per-node-range, no barriers ----------------
// gid sorted. Warp gw handles contiguous nodes [gw*per, min(+per, N)).
// Lane owns 4 dims. Per-graph accumulators flushed by atomics at boundaries.
#define POOL_BLOCKS 400
#define POOL_TPB 256
__global__ void pool_kernel(const float* __restrict__ h,
                            const int* __restrict__ gid,
                            const float* __restrict__ Wp,
                            const float* __restrict__ bp,
                            float* __restrict__ out, int N) {
    int gw = (blockIdx.x * POOL_TPB + threadIdx.x) >> 5;
    int lane = threadIdx.x & 31;
    const int nwarps = POOL_BLOCKS * (POOL_TPB / 32);
    int per = (N + nwarps - 1) / nwarps;
    int n0 = gw * per;
    if (n0 >= N) return;
    int n1 = n0 + per; if (n1 > N) n1 = N;

    float4 wp = ((const float4*)Wp)[lane];
    float bpv = bp[0];

    int gcur = __ldg(&gid[n0]);
    float4 ls = make_float4(0.f, 0.f, 0.f, 0.f);
    float4 lm = make_float4(0.f, 0.f, 0.f, 0.f);
    const float4* h4 = (const float4*)h;

    for (int n = n0; n < n1; n++) {
        int g = __ldg(&gid[n]);
        if (g != gcur) {
            float* os = &out[gcur * 2 * HDIM + lane * 4];
            float* om = os + HDIM;
            atomicAdd(&os[0], ls.x); atomicAdd(&os[1], ls.y);
            atomicAdd(&os[2], ls.z); atomicAdd(&os[3], ls.w);
            atomicMax((int*)&om[0], __float_as_int(lm.x));
            atomicMax((int*)&om[1], __float_as_int(lm.y));
            atomicMax((int*)&om[2], __float_as_int(lm.z));
            atomicMax((int*)&om[3], __float_as_int(lm.w));
            ls = make_float4(0.f, 0.f, 0.f, 0.f);
            lm = make_float4(0.f, 0.f, 0.f, 0.f);
            gcur = g;
        }
        float4 v = __ldg(&h4[(size_t)n * 32 + lane]);
        float p = v.x * wp.x + v.y * wp.y + v.z * wp.z + v.w * wp.w;
        #pragma unroll
        for (int o = 16; o > 0; o >>= 1)
            p += __shfl_xor_sync(0xFFFFFFFFu, p, o);
        float w = 1.0f / (1.0f + expf(-(p + bpv)));
        ls.x += v.x * w; ls.y += v.y * w; ls.z += v.z * w; ls.w += v.w * w;
        lm.x = fmaxf(lm.x, v.x); lm.y = fmaxf(lm.y, v.y);
        lm.z = fmaxf(lm.z, v.z); lm.w = fmaxf(lm.w, v.w);
    }
    // final flush
    float* os = &out[gcur * 2 * HDIM + lane * 4];
    float* om = os + HDIM;
    atomicAdd(&os[0], ls.x); atomicAdd(&os[1], ls.y);
    atomicAdd(&os[2], ls.z); atomicAdd(&os[3], ls.w);
    atomicMax((int*)&om[0], __float_as_int(lm.x));
    atomicMax((int*)&om[1], __float_as_int(lm.y));
    atomicMax((int*)&om[2], __float_as_int(lm.z));
    atomicMax((int*)&om[3], __float_as_int(lm.w));
}

// ---------------- launch ----------------
extern "C" void kernel_launch(void* const* d_in, const int* in_sizes, int n_in,
                              void* d_out, int out_size) {
    const float* node_feats = (const float*)d_in[0];
    const int*   src        = (const int*)d_in[1];
    const int*   dst        = (const int*)d_in[2];
    const int*   gid        = (const int*)d_in[3];
    const float* W1 = (const float*)d_in[4];  const float* b1 = (const float*)d_in[5];
    const float* W2 = (const float*)d_in[6];  const float* b2 = (const float*)d_in[7];
    const float* W3 = (const float*)d_in[8];  const float* b3 = (const float*)d_in[9];
    const float* Wp = (const float*)d_in[10]; const float* bp = (const float*)d_in[11];
    float* out = (float*)d_out;

    const int N = in_sizes[0] / HDIM;
    const int E = in_sizes[1];

    float *phA, *pns, *pnd;
    __half *pY, *pu;
    __nv_bfloat16 *pWhi, *pWlo;
    int *pod, *pid_, *poff, *pcur, *pcsr, *pbs;
    cudaGetSymbolAddress((void**)&pY,   g_Y);
    cudaGetSymbolAddress((void**)&pu,   g_u);
    cudaGetSymbolAddress((void**)&phA,  g_hA);
    cudaGetSymbolAddress((void**)&pWhi, g_Whi);
    cudaGetSymbolAddress((void**)&pWlo, g_Wlo);
    cudaGetSymbolAddress((void**)&pns, g_ns);
    cudaGetSymbolAddress((void**)&pnd, g_nd);
    cudaGetSymbolAddress((void**)&pod, g_odeg);
    cudaGetSymbolAddress((void**)&pid_, g_ideg);
    cudaGetSymbolAddress((void**)&poff, g_off);
    cudaGetSymbolAddress((void**)&pcur, g_cursor);
    cudaGetSymbolAddress((void**)&pcsr, g_csr_src);
    cudaGetSymbolAddress((void**)&pbs, g_bsums);

    cudaFuncSetAttribute(mma_gemm_kernel,
                         cudaFuncAttributeMaxDynamicSharedMemorySize, SMEM_MMA);

    const int nblk_scan = (N + SCAN_BLK - 1) / SCAN_BLK;
    const int gemm_grid = (N + 127) / 128;
    const int gather_blocks = (int)(((long long)N * 32 + 255) / 256);

    // --- fork: CSR/norm build on side stream; conversions + GEMM1 on main ---
    cudaStream_t sB;
    cudaStreamCreateWithFlags(&sB, cudaStreamNonBlocking);
    cudaEvent_t evFork, evJoin;
    cudaEventCreateWithFlags(&evFork, cudaEventDisableTiming);
    cudaEventCreateWithFlags(&evJoin, cudaEventDisableTiming);

    cudaEventRecord(evFork, 0);
    cudaStreamWaitEvent(sB, evFork, 0);

    zero_deg_kernel<<<(N + 255) / 256, 256, 0, sB>>>(pod, pid_, N);
    count_deg_kernel<<<(E + 255) / 256, 256, 0, sB>>>(src, dst, pod, pid_, E);
    norms_kernel<<<(N + 255) / 256, 256, 0, sB>>>(pod, pid_, pns, pnd, N);
    blocksum_kernel<<<nblk_scan, SCAN_BLK, 0, sB>>>(pid_, pbs, N);
    scan_bsums_kernel<<<1, MAX_BLKS, 0, sB>>>(pbs, nblk_scan);
    write_offsets_kernel<<<nblk_scan, SCAN_BLK, 0, sB>>>(pid_, pbs, poff, pcur, N);
    fill_csr_kernel<<<(E + 255) / 256, 256, 0, sB>>>(src, dst, pcur, pcsr, E);
    zero_out_kernel<<<(out_size + 255) / 256, 256, 0, sB>>>(out, out_size);

    // main: W + X conversion, GEMM1 (independent of norms/CSR)
    convertW_kernel<<<(3 * HDIM * HDIM + 255) / 256, 256>>>(W1, W2, W3, pWhi, pWlo);
    convertX_kernel<<<(N * 32 + 255) / 256, 256>>>(node_feats, pu, N * 32);
    mma_gemm_kernel<<<gemm_grid, 512, SMEM_MMA>>>(pu, pWhi, pWlo, pY, N);

    cudaEventRecord(evJoin, sB);
    cudaStreamWaitEvent(0, evJoin, 0);

    // --- layer 1 gather (per-edge ns), then layers 2-3 ---
    gather_kernel<<<gather_blocks, 256>>>(pY, poff, pid_, pcsr, pns, pnd, b1,
                                          pu, phA, 0, N);
    mma_gemm_kernel<<<gemm_grid, 512, SMEM_MMA>>>(pu,
                                                  pWhi + HDIM * HDIM,
                                                  pWlo + HDIM * HDIM, pY, N);
    gather_kernel<<<gather_blocks, 256>>>(pY, poff, pid_, pcsr, pns, pnd, b2,
                                          pu, phA, 1, N);
    mma_gemm_kernel<<<gemm_grid, 512, SMEM_MMA>>>(pu,
                                                  pWhi + 2 * HDIM * HDIM,
                                                  pWlo + 2 * HDIM * HDIM, pY, N);
    gather_kernel<<<gather_blocks, 256>>>(pY, poff, pid_, pcsr, pns, pnd, b3,
                                          pu, phA, 2, N);

    pool_kernel<<<POOL_BLOCKS, POOL_TPB>>>(phA, gid, Wp, bp, out, N);
    // single side stream + 2 events, not destroyed (round-6-proven pattern)
}